// round 1
// baseline (speedup 1.0000x reference)
#include <cuda_runtime.h>
#include <cuda_bf16.h>
#include <math.h>

// ---------------------------------------------------------------------------
// Model constants
// ---------------------------------------------------------------------------
#define BB       8
#define LL       2048
#define BLTOT    (BB*LL)        // 16384
#define DM       512
#define DI       1024           // d_inner
#define DS       16             // d_state
#define DTR      32             // dt_rank
#define XDW      64             // dt_rank + 2*d_state
#define NL       4
#define DCONV    4
#define DHID     256
// scan chunking
#define NCHUNK   16
#define CLEN     (LL/NCHUNK)    // 128
#define NCHAIN   (BB*DI)        // 8192

// ---------------------------------------------------------------------------
// Scratch (device globals; allocation APIs are forbidden)
// ---------------------------------------------------------------------------
__device__ float g_x0  [BLTOT*DM];     // ping
__device__ float g_x1  [BLTOT*DM];     // pong
__device__ float g_xz  [(size_t)BLTOT*2*DI]; // 134 MB
__device__ float g_u   [BLTOT*DI];
__device__ float g_xdbl[BLTOT*XDW];
__device__ float g_dt  [BLTOT*DI];
__device__ float g_y   [BLTOT*DI];
__device__ float g_E   [NCHUNK*DS*NCHAIN];
__device__ float g_P   [NCHUNK*DS*NCHAIN];
__device__ float g_Hi  [NCHUNK*DS*NCHAIN];

// ---------------------------------------------------------------------------
// Embedding: x[b,l,d] = (rna!=0) * (seq_emb[rna] + tissue_emb[tissue[b]])
// ---------------------------------------------------------------------------
__global__ void embed_kernel(const int* __restrict__ rna,
                             const int* __restrict__ tissue,
                             const float* __restrict__ seq_emb,
                             const float* __restrict__ tis_emb,
                             float* __restrict__ x)
{
    int i = blockIdx.x*256 + threadIdx.x;
    if (i >= BLTOT*DM) return;
    int d  = i & (DM-1);
    int bl = i >> 9;            // log2(DM)=9
    int b  = bl >> 11;          // log2(LL)=11
    int tok = rna[bl];
    float v = 0.f;
    if (tok != 0)
        v = seq_emb[tok*DM + d] + tis_emb[tissue[b]*DM + d];
    x[i] = v;
}

// ---------------------------------------------------------------------------
// Tiled fp32 GEMM:  C[M,N] = A[M,K] * W[N,K]^T   (both row-major, K contiguous)
// Requires M%BM==0, N%BN==0, K%BK==0, lda/ldb multiples of 4.
// EPI: 0 = none, 1 = softplus(acc + bias[col])
// ---------------------------------------------------------------------------
template<int BM, int BN, int BK, int TM, int TN, int EPI>
__global__ __launch_bounds__(256)
void gemm_nt(const float* __restrict__ A, int lda,
             const float* __restrict__ W, int ldb,
             float* __restrict__ C, int ldc,
             int K, const float* __restrict__ bias)
{
    __shared__ float As[BK][BM];
    __shared__ float Bs[BK][BN];

    const int tid = threadIdx.x;
    const int m0 = blockIdx.y * BM;
    const int n0 = blockIdx.x * BN;
    constexpr int TCOLS = BN / TN;          // threads per row of micro-tiles
    const int tm = tid / TCOLS;
    const int tn = tid % TCOLS;

    constexpr int AV = (BM*BK)/(4*256);     // float4 loads per thread (A)
    constexpr int BV = (BN*BK)/(4*256);     // float4 loads per thread (B)
    static_assert(AV >= 1 && BV >= 1, "tile too small");

    float acc[TM][TN];
    #pragma unroll
    for (int i=0;i<TM;i++)
        #pragma unroll
        for (int j=0;j<TN;j++) acc[i][j] = 0.f;

    for (int k0 = 0; k0 < K; k0 += BK) {
        float4 av[AV], bv[BV];
        #pragma unroll
        for (int i=0;i<AV;i++) {
            int q  = tid + i*256;
            int r  = q / (BK/4);
            int c4 = (q % (BK/4))*4;
            av[i] = *(const float4*)(A + (size_t)(m0+r)*lda + k0 + c4);
        }
        #pragma unroll
        for (int i=0;i<BV;i++) {
            int q  = tid + i*256;
            int r  = q / (BK/4);
            int c4 = (q % (BK/4))*4;
            bv[i] = *(const float4*)(W + (size_t)(n0+r)*ldb + k0 + c4);
        }
        __syncthreads();
        #pragma unroll
        for (int i=0;i<AV;i++) {
            int q  = tid + i*256;
            int r  = q / (BK/4);
            int c4 = (q % (BK/4))*4;
            As[c4+0][r]=av[i].x; As[c4+1][r]=av[i].y;
            As[c4+2][r]=av[i].z; As[c4+3][r]=av[i].w;
        }
        #pragma unroll
        for (int i=0;i<BV;i++) {
            int q  = tid + i*256;
            int r  = q / (BK/4);
            int c4 = (q % (BK/4))*4;
            Bs[c4+0][r]=bv[i].x; Bs[c4+1][r]=bv[i].y;
            Bs[c4+2][r]=bv[i].z; Bs[c4+3][r]=bv[i].w;
        }
        __syncthreads();

        #pragma unroll
        for (int kk=0; kk<BK; kk++) {
            float a[TM], bb[TN];
            #pragma unroll
            for (int i=0;i<TM;i+=4)
                *(float4*)&a[i] = *(const float4*)&As[kk][tm*TM+i];
            #pragma unroll
            for (int j=0;j<TN;j+=4)
                *(float4*)&bb[j] = *(const float4*)&Bs[kk][tn*TN+j];
            #pragma unroll
            for (int i=0;i<TM;i++)
                #pragma unroll
                for (int j=0;j<TN;j++)
                    acc[i][j] = fmaf(a[i], bb[j], acc[i][j]);
        }
    }

    #pragma unroll
    for (int i=0;i<TM;i++) {
        int row = m0 + tm*TM + i;
        #pragma unroll
        for (int j=0;j<TN;j++) {
            int col = n0 + tn*TN + j;
            float v = acc[i][j];
            if (EPI == 1) {
                v += bias[col];
                v = (v > 20.f) ? v : log1pf(__expf(v));
            }
            C[(size_t)row*ldc + col] = v;
        }
    }
}

// ---------------------------------------------------------------------------
// Causal depthwise conv (k=4) + bias + SiLU.  xz cols [0,DI) are the conv in.
// ---------------------------------------------------------------------------
__global__ void conv_silu_kernel(const float* __restrict__ xz,
                                 const float* __restrict__ cw,
                                 const float* __restrict__ cb,
                                 float* __restrict__ u)
{
    int i = blockIdx.x*256 + threadIdx.x;
    if (i >= BLTOT*DI) return;
    int c  = i & (DI-1);
    int bl = i >> 10;
    int l  = bl & (LL-1);
    int b  = bl >> 11;
    float acc = cb[c];
    #pragma unroll
    for (int k=0;k<DCONV;k++) {
        int ll = l + k - (DCONV-1);
        if (ll >= 0)
            acc = fmaf(xz[((size_t)((b<<11)+ll))*(2*DI) + c], cw[c*DCONV+k], acc);
    }
    u[i] = acc / (1.f + __expf(-acc));   // silu
}

// ---------------------------------------------------------------------------
// Selective scan, chunked two-pass.
// Chains: (b,d) with 16 states in registers.  16 chunks of 128 steps.
// Fast path (detected at runtime): A[d][n] == A[d][0]*(n+1)  =>  dA_n = p^(n+1)
// ---------------------------------------------------------------------------
__global__ void scan_phaseA(const float* __restrict__ dt,
                            const float* __restrict__ u,
                            const float* __restrict__ xdbl,
                            const float* __restrict__ Alog,
                            float* __restrict__ E,
                            float* __restrict__ P)
{
    const int d = blockIdx.x*128 + threadIdx.x;
    const int g = blockIdx.y;
    const int b = blockIdx.z;
    const int chain = b*DI + d;

    float A[DS];
    #pragma unroll
    for (int n=0;n<DS;n++) A[n] = -expf(Alog[d*DS+n]);
    bool fast = true;
    #pragma unroll
    for (int n=1;n<DS;n++)
        fast = fast && (fabsf(A[n] - A[0]*(float)(n+1)) <= 1e-4f*fabsf(A[n]) + 1e-6f);

    float h[DS], ap[DS];
    #pragma unroll
    for (int n=0;n<DS;n++) { h[n]=0.f; ap[n]=1.f; }
    float Pp = 1.f;

    __shared__ float sB[16][DS];
    const int bl0 = b*LL + g*CLEN;

    for (int t0=0; t0<CLEN; t0+=16) {
        __syncthreads();
        for (int q=threadIdx.x; q<16*DS; q+=128) {
            int j = q >> 4, n = q & 15;
            sB[j][n] = xdbl[(bl0+t0+j)*XDW + DTR + n];
        }
        __syncthreads();
        for (int t=0;t<16;t++) {
            int idx = bl0 + t0 + t;
            float ld = dt[idx*DI + d];
            float s  = ld * u[idx*DI + d];
            if (fast) {
                float p = __expf(ld*A[0]);
                Pp *= p;
                float pw = p;
                #pragma unroll
                for (int n=0;n<DS;n++) { h[n] = fmaf(pw, h[n], s*sB[t][n]); pw *= p; }
            } else {
                #pragma unroll
                for (int n=0;n<DS;n++) {
                    float a = __expf(ld*A[n]);
                    ap[n] *= a;
                    h[n] = fmaf(a, h[n], s*sB[t][n]);
                }
            }
        }
    }
    if (fast) {
        float pw = Pp;
        #pragma unroll
        for (int n=0;n<DS;n++) { ap[n] = pw; pw *= Pp; }
    }
    #pragma unroll
    for (int n=0;n<DS;n++) {
        E[(g*DS+n)*NCHAIN + chain] = h[n];
        P[(g*DS+n)*NCHAIN + chain] = ap[n];
    }
}

__global__ void scan_phaseB(const float* __restrict__ E,
                            const float* __restrict__ P,
                            float* __restrict__ Hi)
{
    int c = blockIdx.x*256 + threadIdx.x;
    if (c >= NCHAIN) return;
    #pragma unroll
    for (int n=0;n<DS;n++) {
        float carry = 0.f;
        #pragma unroll
        for (int g=0;g<NCHUNK;g++) {
            int o = (g*DS+n)*NCHAIN + c;
            Hi[o] = carry;
            carry = fmaf(P[o], carry, E[o]);
        }
    }
}

__global__ void scan_phaseC(const float* __restrict__ dt,
                            const float* __restrict__ u,
                            const float* __restrict__ xdbl,
                            const float* __restrict__ xz,
                            const float* __restrict__ Alog,
                            const float* __restrict__ Dpar,
                            const float* __restrict__ Hi,
                            float* __restrict__ yout)
{
    const int d = blockIdx.x*128 + threadIdx.x;
    const int g = blockIdx.y;
    const int b = blockIdx.z;
    const int chain = b*DI + d;

    float A[DS];
    #pragma unroll
    for (int n=0;n<DS;n++) A[n] = -expf(Alog[d*DS+n]);
    bool fast = true;
    #pragma unroll
    for (int n=1;n<DS;n++)
        fast = fast && (fabsf(A[n] - A[0]*(float)(n+1)) <= 1e-4f*fabsf(A[n]) + 1e-6f);

    float h[DS];
    #pragma unroll
    for (int n=0;n<DS;n++) h[n] = Hi[(g*DS+n)*NCHAIN + chain];
    const float Dp = Dpar[d];

    __shared__ float sBC[16][2*DS];
    const int bl0 = b*LL + g*CLEN;

    for (int t0=0; t0<CLEN; t0+=16) {
        __syncthreads();
        for (int q=threadIdx.x; q<16*2*DS; q+=128) {
            int j = q >> 5, m = q & 31;
            sBC[j][m] = xdbl[(bl0+t0+j)*XDW + DTR + m];
        }
        __syncthreads();
        for (int t=0;t<16;t++) {
            int idx = bl0 + t0 + t;
            float ld = dt[idx*DI + d];
            float lu = u [idx*DI + d];
            float s  = ld * lu;
            float y  = 0.f;
            if (fast) {
                float p = __expf(ld*A[0]);
                float pw = p;
                #pragma unroll
                for (int n=0;n<DS;n++) {
                    h[n] = fmaf(pw, h[n], s*sBC[t][n]);
                    y    = fmaf(h[n], sBC[t][DS+n], y);
                    pw *= p;
                }
            } else {
                #pragma unroll
                for (int n=0;n<DS;n++) {
                    float a = __expf(ld*A[n]);
                    h[n] = fmaf(a, h[n], s*sBC[t][n]);
                    y    = fmaf(h[n], sBC[t][DS+n], y);
                }
            }
            float z   = xz[(size_t)idx*(2*DI) + DI + d];
            float sig = 1.f / (1.f + __expf(-z));
            yout[idx*DI + d] = (y + lu*Dp) * z * sig;
        }
    }
}

// ---------------------------------------------------------------------------
// Head: out[b] = relu(x_last @ W1^T + b1) @ W2^T + b2
// ---------------------------------------------------------------------------
__global__ void head_kernel(const float* __restrict__ x,
                            const int* __restrict__ lens,
                            const float* __restrict__ W1,
                            const float* __restrict__ b1,
                            const float* __restrict__ W2,
                            const float* __restrict__ b2,
                            float* __restrict__ out)
{
    __shared__ float xs[DM];
    __shared__ float red[DHID];
    const int b = blockIdx.x;
    const int tid = threadIdx.x;
    const int l = lens[b] - 1;
    const float* xr = x + ((size_t)(b*LL + l))*DM;
    for (int i=tid; i<DM; i+=DHID) xs[i] = xr[i];
    __syncthreads();
    float acc = b1[tid];
    const float* w = W1 + tid*DM;
    #pragma unroll 4
    for (int d0=0; d0<DM; d0+=4) {
        float4 wv = *(const float4*)(w + d0);
        acc = fmaf(wv.x, xs[d0+0], acc);
        acc = fmaf(wv.y, xs[d0+1], acc);
        acc = fmaf(wv.z, xs[d0+2], acc);
        acc = fmaf(wv.w, xs[d0+3], acc);
    }
    float hh = fmaxf(acc, 0.f);
    red[tid] = hh * W2[tid];
    __syncthreads();
    for (int s=DHID/2; s>0; s>>=1) {
        if (tid < s) red[tid] += red[tid+s];
        __syncthreads();
    }
    if (tid == 0) out[b] = red[0] + b2[0];
}

// ---------------------------------------------------------------------------
// Host launcher
// ---------------------------------------------------------------------------
extern "C" void kernel_launch(void* const* d_in, const int* in_sizes, int n_in,
                              void* d_out, int out_size)
{
    const int*   rna     = (const int*)  d_in[0];
    const int*   tissue  = (const int*)  d_in[1];
    const int*   lens    = (const int*)  d_in[2];
    const float* seq_emb = (const float*)d_in[3];
    const float* tis_emb = (const float*)d_in[4];
    const float* W_in    = (const float*)d_in[5];
    const float* conv_w  = (const float*)d_in[6];
    const float* conv_b  = (const float*)d_in[7];
    const float* W_xp    = (const float*)d_in[8];
    const float* W_dt    = (const float*)d_in[9];
    const float* b_dt    = (const float*)d_in[10];
    const float* A_log   = (const float*)d_in[11];
    const float* D_par   = (const float*)d_in[12];
    const float* W_out   = (const float*)d_in[13];
    const float* W1      = (const float*)d_in[14];
    const float* b1      = (const float*)d_in[15];
    const float* W2      = (const float*)d_in[16];
    const float* b2      = (const float*)d_in[17];

    float *px0, *px1, *pxz, *pu, *pxd, *pdt, *py, *pE, *pP, *pHi;
    cudaGetSymbolAddress((void**)&px0, g_x0);
    cudaGetSymbolAddress((void**)&px1, g_x1);
    cudaGetSymbolAddress((void**)&pxz, g_xz);
    cudaGetSymbolAddress((void**)&pu,  g_u);
    cudaGetSymbolAddress((void**)&pxd, g_xdbl);
    cudaGetSymbolAddress((void**)&pdt, g_dt);
    cudaGetSymbolAddress((void**)&py,  g_y);
    cudaGetSymbolAddress((void**)&pE,  g_E);
    cudaGetSymbolAddress((void**)&pP,  g_P);
    cudaGetSymbolAddress((void**)&pHi, g_Hi);

    embed_kernel<<<(BLTOT*DM+255)/256, 256>>>(rna, tissue, seq_emb, tis_emb, px0);

    float* xin  = px0;
    float* xout = px1;
    for (int i=0; i<NL; i++) {
        // in-proj: [16384,512] x [2048,512]^T -> xz [16384,2048]
        gemm_nt<128,128,16,8,8,0><<<dim3((2*DI)/128, BLTOT/128), 256>>>(
            xin, DM, W_in + (size_t)i*2*DI*DM, DM, pxz, 2*DI, DM, nullptr);
        // conv + silu -> u
        conv_silu_kernel<<<(BLTOT*DI+255)/256, 256>>>(
            pxz, conv_w + i*DI*DCONV, conv_b + i*DI, pu);
        // x-proj: [16384,1024] x [64,1024]^T -> xdbl [16384,64]
        gemm_nt<128,64,16,8,4,0><<<dim3(XDW/64, BLTOT/128), 256>>>(
            pu, DI, W_xp + (size_t)i*XDW*DI, DI, pxd, XDW, DI, nullptr);
        // dt: softplus([16384,32] x [1024,32]^T + b_dt) -> dt [16384,1024]
        gemm_nt<128,128,16,8,8,1><<<dim3(DI/128, BLTOT/128), 256>>>(
            pxd, XDW, W_dt + (size_t)i*DI*DTR, DTR, pdt, DI, DTR, b_dt + i*DI);
        // selective scan (chunked, fused gate) -> y
        scan_phaseA<<<dim3(DI/128, NCHUNK, BB), 128>>>(
            pdt, pu, pxd, A_log + (size_t)i*DI*DS, pE, pP);
        scan_phaseB<<<(NCHAIN+255)/256, 256>>>(pE, pP, pHi);
        scan_phaseC<<<dim3(DI/128, NCHUNK, BB), 128>>>(
            pdt, pu, pxd, pxz, A_log + (size_t)i*DI*DS, D_par + i*DI, pHi, py);
        // out-proj: [16384,1024] x [512,1024]^T -> x_next [16384,512]
        gemm_nt<128,128,16,8,8,0><<<dim3(DM/128, BLTOT/128), 256>>>(
            py, DI, W_out + (size_t)i*DM*DI, DI, xout, DM, DI, nullptr);

        float* tmp = xin; xin = xout; xout = tmp;
    }

    head_kernel<<<BB, DHID>>>(xin, lens, W1, b1, W2, b2, (float*)d_out);
}

// round 3
// speedup vs baseline: 1.2779x; 1.2779x over previous
#include <cuda_runtime.h>
#include <cuda_bf16.h>
#include <cstdint>
#include <math.h>
#include <mma.h>

using namespace nvcuda;

// ---------------------------------------------------------------------------
// Model constants
// ---------------------------------------------------------------------------
#define BB       8
#define LL       2048
#define BLTOT    (BB*LL)        // 16384
#define DM       512
#define DI       1024           // d_inner
#define DS       16             // d_state
#define DTR      32             // dt_rank
#define XDW      64             // dt_rank + 2*d_state
#define NL       4
#define DCONV    4
#define DHID     256
// scan chunking
#define NCHUNK   16
#define CLEN     (LL/NCHUNK)    // 128
#define NCHAIN   (BB*DI)        // 8192

// ---------------------------------------------------------------------------
// Scratch (device globals; allocation APIs are forbidden)
// ---------------------------------------------------------------------------
__device__ float g_x0  [BLTOT*DM];     // ping
__device__ float g_x1  [BLTOT*DM];     // pong
__device__ float g_xz  [(size_t)BLTOT*2*DI]; // 134 MB
__device__ float g_u   [BLTOT*DI];
__device__ float g_xdbl[BLTOT*XDW];
__device__ float g_dt  [BLTOT*DI];
__device__ float g_y   [BLTOT*DI];
__device__ float g_E   [NCHUNK*DS*NCHAIN];
__device__ float g_P   [NCHUNK*DS*NCHAIN];
__device__ float g_Hi  [NCHUNK*DS*NCHAIN];

// ---------------------------------------------------------------------------
// Embedding
// ---------------------------------------------------------------------------
__global__ void embed_kernel(const int* __restrict__ rna,
                             const int* __restrict__ tissue,
                             const float* __restrict__ seq_emb,
                             const float* __restrict__ tis_emb,
                             float* __restrict__ x)
{
    int i = blockIdx.x*256 + threadIdx.x;
    if (i >= BLTOT*DM) return;
    int d  = i & (DM-1);
    int bl = i >> 9;
    int b  = bl >> 11;
    int tok = rna[bl];
    float v = 0.f;
    if (tok != 0)
        v = seq_emb[tok*DM + d] + tis_emb[tissue[b]*DM + d];
    x[i] = v;
}

// ---------------------------------------------------------------------------
// TF32 tensor-core GEMM:  C[M,N] = A[M,K] * W[N,K]^T  (row-major, K contig)
// Double-buffered cp.async, 128x128x32 tiles, 8 warps,
// warp tile WM x WN built from m16n16k8 wmma tiles.
// ---------------------------------------------------------------------------
template<int BM,int BN,int BK,int WM,int WN>
__global__ void gemm_tf32(const float* __restrict__ A, int lda,
                          const float* __restrict__ W, int ldb,
                          float* __restrict__ C, int ldc, int K)
{
    constexpr int WCOLS = BN/WN;
    constexpr int NW = (BM/WM)*WCOLS;
    constexpr int NT = NW*32;
    constexpr int LDSH = BK+4;

    extern __shared__ float smem[];
    float* As = smem;                  // 2 * BM * LDSH
    float* Bs = smem + 2*BM*LDSH;      // 2 * BN * LDSH

    const int tid = threadIdx.x;
    const int wid = tid >> 5;
    const int wr  = wid / WCOLS;
    const int wc  = wid % WCOLS;
    const int m0  = blockIdx.y*BM;
    const int n0  = blockIdx.x*BN;

    constexpr int TM = WM/16, TN = WN/16;
    wmma::fragment<wmma::accumulator,16,16,8,float> acc[TM][TN];
    #pragma unroll
    for (int i=0;i<TM;i++)
        #pragma unroll
        for (int j=0;j<TN;j++) wmma::fill_fragment(acc[i][j], 0.f);

    constexpr int AIT = (BM*BK)/(4*NT);
    constexpr int BIT = (BN*BK)/(4*NT);
    static_assert(AIT >= 1 && BIT >= 1, "tile/threads mismatch");

    auto issue = [&](int k0, int buf){
        float* as = As + buf*BM*LDSH;
        float* bs = Bs + buf*BN*LDSH;
        #pragma unroll
        for (int i=0;i<AIT;i++){
            int q = tid + i*NT;
            int r = q/(BK/4); int c = (q%(BK/4))*4;
            unsigned int d = (unsigned int)__cvta_generic_to_shared(as + r*LDSH + c);
            const float* s = A + (size_t)(m0+r)*lda + k0 + c;
            asm volatile("cp.async.cg.shared.global [%0],[%1],16;\n" :: "r"(d), "l"(s));
        }
        #pragma unroll
        for (int i=0;i<BIT;i++){
            int q = tid + i*NT;
            int r = q/(BK/4); int c = (q%(BK/4))*4;
            unsigned int d = (unsigned int)__cvta_generic_to_shared(bs + r*LDSH + c);
            const float* s = W + (size_t)(n0+r)*ldb + k0 + c;
            asm volatile("cp.async.cg.shared.global [%0],[%1],16;\n" :: "r"(d), "l"(s));
        }
        asm volatile("cp.async.commit_group;\n");
    };

    const int KT = K/BK;
    issue(0, 0);
    for (int kt=0; kt<KT; kt++){
        if (kt+1 < KT) {
            issue((kt+1)*BK, (kt+1)&1);
            asm volatile("cp.async.wait_group 1;\n");
        } else {
            asm volatile("cp.async.wait_group 0;\n");
        }
        __syncthreads();

        const float* as = As + (kt&1)*BM*LDSH;
        const float* bs = Bs + (kt&1)*BN*LDSH;
        #pragma unroll
        for (int kk=0; kk<BK/8; kk++){
            wmma::fragment<wmma::matrix_a,16,16,8,wmma::precision::tf32,wmma::row_major> af[TM];
            wmma::fragment<wmma::matrix_b,16,16,8,wmma::precision::tf32,wmma::col_major> bf[TN];
            #pragma unroll
            for (int i=0;i<TM;i++){
                wmma::load_matrix_sync(af[i], as + (wr*WM + i*16)*LDSH + kk*8, LDSH);
                #pragma unroll
                for (int t=0;t<af[i].num_elements;t++)
                    af[i].x[t] = wmma::__float_to_tf32(af[i].x[t]);
            }
            #pragma unroll
            for (int j=0;j<TN;j++){
                wmma::load_matrix_sync(bf[j], bs + (wc*WN + j*16)*LDSH + kk*8, LDSH);
                #pragma unroll
                for (int t=0;t<bf[j].num_elements;t++)
                    bf[j].x[t] = wmma::__float_to_tf32(bf[j].x[t]);
            }
            #pragma unroll
            for (int i=0;i<TM;i++)
                #pragma unroll
                for (int j=0;j<TN;j++)
                    wmma::mma_sync(acc[i][j], af[i], bf[j], acc[i][j]);
        }
        __syncthreads();
    }

    #pragma unroll
    for (int i=0;i<TM;i++)
        #pragma unroll
        for (int j=0;j<TN;j++){
            float* cp = C + (size_t)(m0 + wr*WM + i*16)*ldc + n0 + wc*WN + j*16;
            wmma::store_matrix_sync(cp, acc[i][j], ldc, wmma::mem_row_major);
        }
}

// ---------------------------------------------------------------------------
// SIMT fp32 GEMM (kept for the small, precision-sensitive GEMMs)
// EPI: 0 = none, 1 = softplus(acc + bias[col])
// ---------------------------------------------------------------------------
template<int BM, int BN, int BK, int TM, int TN, int EPI>
__global__ __launch_bounds__(256)
void gemm_nt(const float* __restrict__ A, int lda,
             const float* __restrict__ W, int ldb,
             float* __restrict__ C, int ldc,
             int K, const float* __restrict__ bias)
{
    __shared__ float As[BK][BM];
    __shared__ float Bs[BK][BN];

    const int tid = threadIdx.x;
    const int m0 = blockIdx.y * BM;
    const int n0 = blockIdx.x * BN;
    constexpr int TCOLS = BN / TN;
    const int tm = tid / TCOLS;
    const int tn = tid % TCOLS;

    constexpr int AV = (BM*BK)/(4*256);
    constexpr int BV = (BN*BK)/(4*256);
    static_assert(AV >= 1 && BV >= 1, "tile too small");

    float acc[TM][TN];
    #pragma unroll
    for (int i=0;i<TM;i++)
        #pragma unroll
        for (int j=0;j<TN;j++) acc[i][j] = 0.f;

    for (int k0 = 0; k0 < K; k0 += BK) {
        float4 av[AV], bv[BV];
        #pragma unroll
        for (int i=0;i<AV;i++) {
            int q  = tid + i*256;
            int r  = q / (BK/4);
            int c4 = (q % (BK/4))*4;
            av[i] = *(const float4*)(A + (size_t)(m0+r)*lda + k0 + c4);
        }
        #pragma unroll
        for (int i=0;i<BV;i++) {
            int q  = tid + i*256;
            int r  = q / (BK/4);
            int c4 = (q % (BK/4))*4;
            bv[i] = *(const float4*)(W + (size_t)(n0+r)*ldb + k0 + c4);
        }
        __syncthreads();
        #pragma unroll
        for (int i=0;i<AV;i++) {
            int q  = tid + i*256;
            int r  = q / (BK/4);
            int c4 = (q % (BK/4))*4;
            As[c4+0][r]=av[i].x; As[c4+1][r]=av[i].y;
            As[c4+2][r]=av[i].z; As[c4+3][r]=av[i].w;
        }
        #pragma unroll
        for (int i=0;i<BV;i++) {
            int q  = tid + i*256;
            int r  = q / (BK/4);
            int c4 = (q % (BK/4))*4;
            Bs[c4+0][r]=bv[i].x; Bs[c4+1][r]=bv[i].y;
            Bs[c4+2][r]=bv[i].z; Bs[c4+3][r]=bv[i].w;
        }
        __syncthreads();

        #pragma unroll
        for (int kk=0; kk<BK; kk++) {
            float a[TM], bb[TN];
            #pragma unroll
            for (int i=0;i<TM;i+=4)
                *(float4*)&a[i] = *(const float4*)&As[kk][tm*TM+i];
            #pragma unroll
            for (int j=0;j<TN;j+=4)
                *(float4*)&bb[j] = *(const float4*)&Bs[kk][tn*TN+j];
            #pragma unroll
            for (int i=0;i<TM;i++)
                #pragma unroll
                for (int j=0;j<TN;j++)
                    acc[i][j] = fmaf(a[i], bb[j], acc[i][j]);
        }
    }

    #pragma unroll
    for (int i=0;i<TM;i++) {
        int row = m0 + tm*TM + i;
        #pragma unroll
        for (int j=0;j<TN;j++) {
            int col = n0 + tn*TN + j;
            float v = acc[i][j];
            if (EPI == 1) {
                v += bias[col];
                v = (v > 20.f) ? v : log1pf(__expf(v));
            }
            C[(size_t)row*ldc + col] = v;
        }
    }
}

// ---------------------------------------------------------------------------
// Causal depthwise conv (k=4) + bias + SiLU
// ---------------------------------------------------------------------------
__global__ void conv_silu_kernel(const float* __restrict__ xz,
                                 const float* __restrict__ cw,
                                 const float* __restrict__ cb,
                                 float* __restrict__ u)
{
    int i = blockIdx.x*256 + threadIdx.x;
    if (i >= BLTOT*DI) return;
    int c  = i & (DI-1);
    int bl = i >> 10;
    int l  = bl & (LL-1);
    int b  = bl >> 11;
    float acc = cb[c];
    #pragma unroll
    for (int k=0;k<DCONV;k++) {
        int ll = l + k - (DCONV-1);
        if (ll >= 0)
            acc = fmaf(xz[((size_t)((b<<11)+ll))*(2*DI) + c], cw[c*DCONV+k], acc);
    }
    u[i] = acc / (1.f + __expf(-acc));
}

// ---------------------------------------------------------------------------
// Selective scan, chunked two-pass
// ---------------------------------------------------------------------------
__global__ void scan_phaseA(const float* __restrict__ dt,
                            const float* __restrict__ u,
                            const float* __restrict__ xdbl,
                            const float* __restrict__ Alog,
                            float* __restrict__ E,
                            float* __restrict__ P)
{
    const int d = blockIdx.x*128 + threadIdx.x;
    const int g = blockIdx.y;
    const int b = blockIdx.z;
    const int chain = b*DI + d;

    float A[DS];
    #pragma unroll
    for (int n=0;n<DS;n++) A[n] = -expf(Alog[d*DS+n]);
    bool fast = true;
    #pragma unroll
    for (int n=1;n<DS;n++)
        fast = fast && (fabsf(A[n] - A[0]*(float)(n+1)) <= 1e-4f*fabsf(A[n]) + 1e-6f);

    float h[DS], ap[DS];
    #pragma unroll
    for (int n=0;n<DS;n++) { h[n]=0.f; ap[n]=1.f; }
    float Pp = 1.f;

    __shared__ float sB[16][DS];
    const int bl0 = b*LL + g*CLEN;

    for (int t0=0; t0<CLEN; t0+=16) {
        __syncthreads();
        for (int q=threadIdx.x; q<16*DS; q+=128) {
            int j = q >> 4, n = q & 15;
            sB[j][n] = xdbl[(bl0+t0+j)*XDW + DTR + n];
        }
        __syncthreads();
        for (int t=0;t<16;t++) {
            int idx = bl0 + t0 + t;
            float ld = dt[idx*DI + d];
            float s  = ld * u[idx*DI + d];
            if (fast) {
                float p = __expf(ld*A[0]);
                Pp *= p;
                float pw = p;
                #pragma unroll
                for (int n=0;n<DS;n++) { h[n] = fmaf(pw, h[n], s*sB[t][n]); pw *= p; }
            } else {
                #pragma unroll
                for (int n=0;n<DS;n++) {
                    float a = __expf(ld*A[n]);
                    ap[n] *= a;
                    h[n] = fmaf(a, h[n], s*sB[t][n]);
                }
            }
        }
    }
    if (fast) {
        float pw = Pp;
        #pragma unroll
        for (int n=0;n<DS;n++) { ap[n] = pw; pw *= Pp; }
    }
    #pragma unroll
    for (int n=0;n<DS;n++) {
        E[(g*DS+n)*NCHAIN + chain] = h[n];
        P[(g*DS+n)*NCHAIN + chain] = ap[n];
    }
}

__global__ void scan_phaseB(const float* __restrict__ E,
                            const float* __restrict__ P,
                            float* __restrict__ Hi)
{
    int c = blockIdx.x*256 + threadIdx.x;
    if (c >= NCHAIN) return;
    #pragma unroll
    for (int n=0;n<DS;n++) {
        float carry = 0.f;
        #pragma unroll
        for (int g=0;g<NCHUNK;g++) {
            int o = (g*DS+n)*NCHAIN + c;
            Hi[o] = carry;
            carry = fmaf(P[o], carry, E[o]);
        }
    }
}

__global__ void scan_phaseC(const float* __restrict__ dt,
                            const float* __restrict__ u,
                            const float* __restrict__ xdbl,
                            const float* __restrict__ xz,
                            const float* __restrict__ Alog,
                            const float* __restrict__ Dpar,
                            const float* __restrict__ Hi,
                            float* __restrict__ yout)
{
    const int d = blockIdx.x*128 + threadIdx.x;
    const int g = blockIdx.y;
    const int b = blockIdx.z;
    const int chain = b*DI + d;

    float A[DS];
    #pragma unroll
    for (int n=0;n<DS;n++) A[n] = -expf(Alog[d*DS+n]);
    bool fast = true;
    #pragma unroll
    for (int n=1;n<DS;n++)
        fast = fast && (fabsf(A[n] - A[0]*(float)(n+1)) <= 1e-4f*fabsf(A[n]) + 1e-6f);

    float h[DS];
    #pragma unroll
    for (int n=0;n<DS;n++) h[n] = Hi[(g*DS+n)*NCHAIN + chain];
    const float Dp = Dpar[d];

    __shared__ float sBC[16][2*DS];
    const int bl0 = b*LL + g*CLEN;

    for (int t0=0; t0<CLEN; t0+=16) {
        __syncthreads();
        for (int q=threadIdx.x; q<16*2*DS; q+=128) {
            int j = q >> 5, m = q & 31;
            sBC[j][m] = xdbl[(bl0+t0+j)*XDW + DTR + m];
        }
        __syncthreads();
        for (int t=0;t<16;t++) {
            int idx = bl0 + t0 + t;
            float ld = dt[idx*DI + d];
            float lu = u [idx*DI + d];
            float s  = ld * lu;
            float y  = 0.f;
            if (fast) {
                float p = __expf(ld*A[0]);
                float pw = p;
                #pragma unroll
                for (int n=0;n<DS;n++) {
                    h[n] = fmaf(pw, h[n], s*sBC[t][n]);
                    y    = fmaf(h[n], sBC[t][DS+n], y);
                    pw *= p;
                }
            } else {
                #pragma unroll
                for (int n=0;n<DS;n++) {
                    float a = __expf(ld*A[n]);
                    h[n] = fmaf(a, h[n], s*sBC[t][n]);
                    y    = fmaf(h[n], sBC[t][DS+n], y);
                }
            }
            float z   = xz[(size_t)idx*(2*DI) + DI + d];
            float sig = 1.f / (1.f + __expf(-z));
            yout[idx*DI + d] = (y + lu*Dp) * z * sig;
        }
    }
}

// ---------------------------------------------------------------------------
// Head
// ---------------------------------------------------------------------------
__global__ void head_kernel(const float* __restrict__ x,
                            const int* __restrict__ lens,
                            const float* __restrict__ W1,
                            const float* __restrict__ b1,
                            const float* __restrict__ W2,
                            const float* __restrict__ b2,
                            float* __restrict__ out)
{
    __shared__ float xs[DM];
    __shared__ float red[DHID];
    const int b = blockIdx.x;
    const int tid = threadIdx.x;
    const int l = lens[b] - 1;
    const float* xr = x + ((size_t)(b*LL + l))*DM;
    for (int i=tid; i<DM; i+=DHID) xs[i] = xr[i];
    __syncthreads();
    float acc = b1[tid];
    const float* w = W1 + tid*DM;
    #pragma unroll 4
    for (int d0=0; d0<DM; d0+=4) {
        float4 wv = *(const float4*)(w + d0);
        acc = fmaf(wv.x, xs[d0+0], acc);
        acc = fmaf(wv.y, xs[d0+1], acc);
        acc = fmaf(wv.z, xs[d0+2], acc);
        acc = fmaf(wv.w, xs[d0+3], acc);
    }
    float hh = fmaxf(acc, 0.f);
    red[tid] = hh * W2[tid];
    __syncthreads();
    for (int s=DHID/2; s>0; s>>=1) {
        if (tid < s) red[tid] += red[tid+s];
        __syncthreads();
    }
    if (tid == 0) out[b] = red[0] + b2[0];
}

// ---------------------------------------------------------------------------
// Host launcher
// ---------------------------------------------------------------------------
extern "C" void kernel_launch(void* const* d_in, const int* in_sizes, int n_in,
                              void* d_out, int out_size)
{
    const int*   rna     = (const int*)  d_in[0];
    const int*   tissue  = (const int*)  d_in[1];
    const int*   lens    = (const int*)  d_in[2];
    const float* seq_emb = (const float*)d_in[3];
    const float* tis_emb = (const float*)d_in[4];
    const float* W_in    = (const float*)d_in[5];
    const float* conv_w  = (const float*)d_in[6];
    const float* conv_b  = (const float*)d_in[7];
    const float* W_xp    = (const float*)d_in[8];
    const float* W_dt    = (const float*)d_in[9];
    const float* b_dt    = (const float*)d_in[10];
    const float* A_log   = (const float*)d_in[11];
    const float* D_par   = (const float*)d_in[12];
    const float* W_out   = (const float*)d_in[13];
    const float* W1      = (const float*)d_in[14];
    const float* b1      = (const float*)d_in[15];
    const float* W2      = (const float*)d_in[16];
    const float* b2      = (const float*)d_in[17];

    float *px0, *px1, *pxz, *pu, *pxd, *pdt, *py, *pE, *pP, *pHi;
    cudaGetSymbolAddress((void**)&px0, g_x0);
    cudaGetSymbolAddress((void**)&px1, g_x1);
    cudaGetSymbolAddress((void**)&pxz, g_xz);
    cudaGetSymbolAddress((void**)&pu,  g_u);
    cudaGetSymbolAddress((void**)&pxd, g_xdbl);
    cudaGetSymbolAddress((void**)&pdt, g_dt);
    cudaGetSymbolAddress((void**)&py,  g_y);
    cudaGetSymbolAddress((void**)&pE,  g_E);
    cudaGetSymbolAddress((void**)&pP,  g_P);
    cudaGetSymbolAddress((void**)&pHi, g_Hi);

    // TF32 GEMM config: 128x128x32, dynamic smem = 2*(128+128)*(32+4)*4 bytes
    constexpr int TFSMEM = (2*128*36 + 2*128*36) * 4;
    cudaFuncSetAttribute(gemm_tf32<128,128,32,32,64>,
                         cudaFuncAttributeMaxDynamicSharedMemorySize, TFSMEM);

    embed_kernel<<<(BLTOT*DM+255)/256, 256>>>(rna, tissue, seq_emb, tis_emb, px0);

    float* xin  = px0;
    float* xout = px1;
    for (int i=0; i<NL; i++) {
        // in-proj: [16384,512] x [2048,512]^T -> xz [16384,2048]  (TF32 TC)
        gemm_tf32<128,128,32,32,64><<<dim3((2*DI)/128, BLTOT/128), 256, TFSMEM>>>(
            xin, DM, W_in + (size_t)i*2*DI*DM, DM, pxz, 2*DI, DM);
        // conv + silu -> u
        conv_silu_kernel<<<(BLTOT*DI+255)/256, 256>>>(
            pxz, conv_w + i*DI*DCONV, conv_b + i*DI, pu);
        // x-proj: [16384,1024] x [64,1024]^T -> xdbl [16384,64]  (fp32 SIMT)
        gemm_nt<128,64,16,8,4,0><<<dim3(XDW/64, BLTOT/128), 256>>>(
            pu, DI, W_xp + (size_t)i*XDW*DI, DI, pxd, XDW, DI, nullptr);
        // dt: softplus([16384,32] x [1024,32]^T + b_dt)  (fp32 SIMT)
        gemm_nt<128,128,16,8,8,1><<<dim3(DI/128, BLTOT/128), 256>>>(
            pxd, XDW, W_dt + (size_t)i*DI*DTR, DTR, pdt, DI, DTR, b_dt + i*DI);
        // selective scan
        scan_phaseA<<<dim3(DI/128, NCHUNK, BB), 128>>>(
            pdt, pu, pxd, A_log + (size_t)i*DI*DS, pE, pP);
        scan_phaseB<<<(NCHAIN+255)/256, 256>>>(pE, pP, pHi);
        scan_phaseC<<<dim3(DI/128, NCHUNK, BB), 128>>>(
            pdt, pu, pxd, pxz, A_log + (size_t)i*DI*DS, D_par + i*DI, pHi, py);
        // out-proj: [16384,1024] x [512,1024]^T -> x_next  (TF32 TC)
        gemm_tf32<128,128,32,32,64><<<dim3(DM/128, BLTOT/128), 256, TFSMEM>>>(
            py, DI, W_out + (size_t)i*DM*DI, DI, xout, DM, DI);

        float* tmp = xin; xin = xout; xout = tmp;
    }

    head_kernel<<<BB, DHID>>>(xin, lens, W1, b1, W2, b2, (float*)d_out);
}

// round 4
// speedup vs baseline: 1.3333x; 1.0433x over previous
#include <cuda_runtime.h>
#include <cuda_bf16.h>
#include <cstdint>
#include <math.h>
#include <mma.h>

using namespace nvcuda;

// ---------------------------------------------------------------------------
// Model constants
// ---------------------------------------------------------------------------
#define BB       8
#define LL       2048
#define BLTOT    (BB*LL)        // 16384
#define DM       512
#define DI       1024           // d_inner
#define DS       16             // d_state
#define DTR      32             // dt_rank
#define XDW      64             // dt_rank + 2*d_state
#define NL       4
#define DCONV    4
#define DHID     256
// scan chunking
#define NCHUNK   32
#define CLEN     (LL/NCHUNK)    // 64
#define NCHAIN   (BB*DI)        // 8192

// ---------------------------------------------------------------------------
// Scratch (device globals; allocation APIs are forbidden)
// ---------------------------------------------------------------------------
__device__ float g_x0  [BLTOT*DM];
__device__ float g_x1  [BLTOT*DM];
__device__ float g_xz  [(size_t)BLTOT*2*DI];
__device__ float g_u   [BLTOT*DI];
__device__ float g_xdbl[BLTOT*XDW];
__device__ float g_dt  [BLTOT*DI];
__device__ float g_y   [BLTOT*DI];
__device__ float g_E   [NCHUNK*DS*NCHAIN];
__device__ float g_P   [NCHUNK*DS*NCHAIN];
__device__ float g_Hi  [NCHUNK*DS*NCHAIN];

// ---------------------------------------------------------------------------
// Embedding
// ---------------------------------------------------------------------------
__global__ void embed_kernel(const int* __restrict__ rna,
                             const int* __restrict__ tissue,
                             const float* __restrict__ seq_emb,
                             const float* __restrict__ tis_emb,
                             float* __restrict__ x)
{
    int i = blockIdx.x*256 + threadIdx.x;
    if (i >= BLTOT*DM) return;
    int d  = i & (DM-1);
    int bl = i >> 9;
    int b  = bl >> 11;
    int tok = rna[bl];
    float v = 0.f;
    if (tok != 0)
        v = seq_emb[tok*DM + d] + tis_emb[tissue[b]*DM + d];
    x[i] = v;
}

// ---------------------------------------------------------------------------
// TF32 tensor-core GEMM v2: C[M,N] = A[M,K] * W[N,K]^T (row-major, K contig)
// 4 warps, 64x64 warp tiles, 3-stage cp.async pipeline, 128x128x32 block tile.
// ---------------------------------------------------------------------------
#define TF_BM 128
#define TF_BN 128
#define TF_BK 32
#define TF_WM 64
#define TF_WN 64
#define TF_NT 128
#define TF_LDSH (TF_BK+4)
#define TF_STG 3
#define TF_ABUF (TF_BM*TF_LDSH)
#define TF_BBUF (TF_BN*TF_LDSH)
#define TF_SMEM (TF_STG*(TF_ABUF+TF_BBUF)*4)

__global__ __launch_bounds__(TF_NT)
void gemm_tf32(const float* __restrict__ A, int lda,
               const float* __restrict__ W, int ldb,
               float* __restrict__ C, int ldc, int K)
{
    extern __shared__ float smem[];
    float* As = smem;                        // TF_STG * TF_ABUF
    float* Bs = smem + TF_STG*TF_ABUF;       // TF_STG * TF_BBUF

    const int tid = threadIdx.x;
    const int wid = tid >> 5;
    const int wr  = wid >> 1;                // 0..1
    const int wc  = wid & 1;                 // 0..1
    const int m0  = blockIdx.y*TF_BM;
    const int n0  = blockIdx.x*TF_BN;

    constexpr int TM = TF_WM/16, TN = TF_WN/16;  // 4 x 4
    wmma::fragment<wmma::accumulator,16,16,8,float> acc[TM][TN];
    #pragma unroll
    for (int i=0;i<TM;i++)
        #pragma unroll
        for (int j=0;j<TN;j++) wmma::fill_fragment(acc[i][j], 0.f);

    constexpr int AIT = (TF_BM*TF_BK)/(4*TF_NT);   // 8
    constexpr int BIT = (TF_BN*TF_BK)/(4*TF_NT);   // 8

    auto issue = [&](int kt, int buf){
        int k0 = kt*TF_BK;
        float* as = As + buf*TF_ABUF;
        float* bs = Bs + buf*TF_BBUF;
        #pragma unroll
        for (int i=0;i<AIT;i++){
            int q = tid + i*TF_NT;
            int r = q >> 3; int c = (q & 7)*4;
            unsigned int d = (unsigned int)__cvta_generic_to_shared(as + r*TF_LDSH + c);
            const float* s = A + (size_t)(m0+r)*lda + k0 + c;
            asm volatile("cp.async.cg.shared.global [%0],[%1],16;\n" :: "r"(d), "l"(s));
        }
        #pragma unroll
        for (int i=0;i<BIT;i++){
            int q = tid + i*TF_NT;
            int r = q >> 3; int c = (q & 7)*4;
            unsigned int d = (unsigned int)__cvta_generic_to_shared(bs + r*TF_LDSH + c);
            const float* s = W + (size_t)(n0+r)*ldb + k0 + c;
            asm volatile("cp.async.cg.shared.global [%0],[%1],16;\n" :: "r"(d), "l"(s));
        }
        asm volatile("cp.async.commit_group;\n");
    };

    const int KT = K/TF_BK;
    issue(0, 0);
    if (KT > 1) issue(1, 1);

    for (int kt=0; kt<KT; kt++){
        if (kt+2 < KT) {
            issue(kt+2, (kt+2)%TF_STG);
            asm volatile("cp.async.wait_group 2;\n");
        } else if (kt+1 < KT) {
            asm volatile("cp.async.wait_group 1;\n");
        } else {
            asm volatile("cp.async.wait_group 0;\n");
        }
        __syncthreads();

        const float* as = As + (kt%TF_STG)*TF_ABUF;
        const float* bs = Bs + (kt%TF_STG)*TF_BBUF;
        #pragma unroll
        for (int kk=0; kk<TF_BK/8; kk++){
            wmma::fragment<wmma::matrix_a,16,16,8,wmma::precision::tf32,wmma::row_major> af[TM];
            wmma::fragment<wmma::matrix_b,16,16,8,wmma::precision::tf32,wmma::col_major> bf[TN];
            #pragma unroll
            for (int i=0;i<TM;i++){
                wmma::load_matrix_sync(af[i], as + (wr*TF_WM + i*16)*TF_LDSH + kk*8, TF_LDSH);
                #pragma unroll
                for (int t=0;t<af[i].num_elements;t++)
                    af[i].x[t] = wmma::__float_to_tf32(af[i].x[t]);
            }
            #pragma unroll
            for (int j=0;j<TN;j++){
                wmma::load_matrix_sync(bf[j], bs + (wc*TF_WN + j*16)*TF_LDSH + kk*8, TF_LDSH);
                #pragma unroll
                for (int t=0;t<bf[j].num_elements;t++)
                    bf[j].x[t] = wmma::__float_to_tf32(bf[j].x[t]);
            }
            #pragma unroll
            for (int i=0;i<TM;i++)
                #pragma unroll
                for (int j=0;j<TN;j++)
                    wmma::mma_sync(acc[i][j], af[i], bf[j], acc[i][j]);
        }
        __syncthreads();   // protect buffer (kt%3) before re-issue next iter
    }

    #pragma unroll
    for (int i=0;i<TM;i++)
        #pragma unroll
        for (int j=0;j<TN;j++){
            float* cp = C + (size_t)(m0 + wr*TF_WM + i*16)*ldc + n0 + wc*TF_WN + j*16;
            wmma::store_matrix_sync(cp, acc[i][j], ldc, wmma::mem_row_major);
        }
}

// ---------------------------------------------------------------------------
// SIMT fp32 GEMM (small GEMMs) — EPI: 0 none, 1 softplus(acc+bias[col])
// ---------------------------------------------------------------------------
template<int BM, int BN, int BK, int TM, int TN, int EPI>
__global__ __launch_bounds__(256)
void gemm_nt(const float* __restrict__ A, int lda,
             const float* __restrict__ W, int ldb,
             float* __restrict__ C, int ldc,
             int K, const float* __restrict__ bias)
{
    __shared__ float As[BK][BM];
    __shared__ float Bs[BK][BN];

    const int tid = threadIdx.x;
    const int m0 = blockIdx.y * BM;
    const int n0 = blockIdx.x * BN;
    constexpr int TCOLS = BN / TN;
    const int tm = tid / TCOLS;
    const int tn = tid % TCOLS;

    constexpr int AV = (BM*BK)/(4*256);
    constexpr int BV = (BN*BK)/(4*256);
    static_assert(AV >= 1 && BV >= 1, "tile too small");

    float acc[TM][TN];
    #pragma unroll
    for (int i=0;i<TM;i++)
        #pragma unroll
        for (int j=0;j<TN;j++) acc[i][j] = 0.f;

    for (int k0 = 0; k0 < K; k0 += BK) {
        float4 av[AV], bv[BV];
        #pragma unroll
        for (int i=0;i<AV;i++) {
            int q  = tid + i*256;
            int r  = q / (BK/4);
            int c4 = (q % (BK/4))*4;
            av[i] = *(const float4*)(A + (size_t)(m0+r)*lda + k0 + c4);
        }
        #pragma unroll
        for (int i=0;i<BV;i++) {
            int q  = tid + i*256;
            int r  = q / (BK/4);
            int c4 = (q % (BK/4))*4;
            bv[i] = *(const float4*)(W + (size_t)(n0+r)*ldb + k0 + c4);
        }
        __syncthreads();
        #pragma unroll
        for (int i=0;i<AV;i++) {
            int q  = tid + i*256;
            int r  = q / (BK/4);
            int c4 = (q % (BK/4))*4;
            As[c4+0][r]=av[i].x; As[c4+1][r]=av[i].y;
            As[c4+2][r]=av[i].z; As[c4+3][r]=av[i].w;
        }
        #pragma unroll
        for (int i=0;i<BV;i++) {
            int q  = tid + i*256;
            int r  = q / (BK/4);
            int c4 = (q % (BK/4))*4;
            Bs[c4+0][r]=bv[i].x; Bs[c4+1][r]=bv[i].y;
            Bs[c4+2][r]=bv[i].z; Bs[c4+3][r]=bv[i].w;
        }
        __syncthreads();

        #pragma unroll
        for (int kk=0; kk<BK; kk++) {
            float a[TM], bb[TN];
            #pragma unroll
            for (int i=0;i<TM;i+=4)
                *(float4*)&a[i] = *(const float4*)&As[kk][tm*TM+i];
            #pragma unroll
            for (int j=0;j<TN;j+=4)
                *(float4*)&bb[j] = *(const float4*)&Bs[kk][tn*TN+j];
            #pragma unroll
            for (int i=0;i<TM;i++)
                #pragma unroll
                for (int j=0;j<TN;j++)
                    acc[i][j] = fmaf(a[i], bb[j], acc[i][j]);
        }
    }

    #pragma unroll
    for (int i=0;i<TM;i++) {
        int row = m0 + tm*TM + i;
        #pragma unroll
        for (int j=0;j<TN;j++) {
            int col = n0 + tn*TN + j;
            float v = acc[i][j];
            if (EPI == 1) {
                v += bias[col];
                v = (v > 20.f) ? v : log1pf(__expf(v));
            }
            C[(size_t)row*ldc + col] = v;
        }
    }
}

// ---------------------------------------------------------------------------
// Causal depthwise conv (k=4) + bias + SiLU
// ---------------------------------------------------------------------------
__global__ void conv_silu_kernel(const float* __restrict__ xz,
                                 const float* __restrict__ cw,
                                 const float* __restrict__ cb,
                                 float* __restrict__ u)
{
    int i = blockIdx.x*256 + threadIdx.x;
    if (i >= BLTOT*DI) return;
    int c  = i & (DI-1);
    int bl = i >> 10;
    int l  = bl & (LL-1);
    int b  = bl >> 11;
    float acc = cb[c];
    #pragma unroll
    for (int k=0;k<DCONV;k++) {
        int ll = l + k - (DCONV-1);
        if (ll >= 0)
            acc = fmaf(xz[((size_t)((b<<11)+ll))*(2*DI) + c], cw[c*DCONV+k], acc);
    }
    u[i] = acc / (1.f + __expf(-acc));
}

// ---------------------------------------------------------------------------
// Selective scan, chunked two-pass (NCHUNK=32, CLEN=64)
// ---------------------------------------------------------------------------
__global__ void scan_phaseA(const float* __restrict__ dt,
                            const float* __restrict__ u,
                            const float* __restrict__ xdbl,
                            const float* __restrict__ Alog,
                            float* __restrict__ E,
                            float* __restrict__ P)
{
    const int d = blockIdx.x*128 + threadIdx.x;
    const int g = blockIdx.y;
    const int b = blockIdx.z;
    const int chain = b*DI + d;

    float A[DS];
    #pragma unroll
    for (int n=0;n<DS;n++) A[n] = -expf(Alog[d*DS+n]);
    bool fast = true;
    #pragma unroll
    for (int n=1;n<DS;n++)
        fast = fast && (fabsf(A[n] - A[0]*(float)(n+1)) <= 1e-4f*fabsf(A[n]) + 1e-6f);

    float h[DS], ap[DS];
    #pragma unroll
    for (int n=0;n<DS;n++) { h[n]=0.f; ap[n]=1.f; }
    float Pp = 1.f;

    __shared__ float sB[16][DS];
    const int bl0 = b*LL + g*CLEN;

    for (int t0=0; t0<CLEN; t0+=16) {
        __syncthreads();
        for (int q=threadIdx.x; q<16*DS; q+=128) {
            int j = q >> 4, n = q & 15;
            sB[j][n] = xdbl[(bl0+t0+j)*XDW + DTR + n];
        }
        __syncthreads();
        for (int t=0;t<16;t++) {
            int idx = bl0 + t0 + t;
            float ld = dt[idx*DI + d];
            float s  = ld * u[idx*DI + d];
            if (fast) {
                float p = __expf(ld*A[0]);
                Pp *= p;
                float pw = p;
                #pragma unroll
                for (int n=0;n<DS;n++) { h[n] = fmaf(pw, h[n], s*sB[t][n]); pw *= p; }
            } else {
                #pragma unroll
                for (int n=0;n<DS;n++) {
                    float a = __expf(ld*A[n]);
                    ap[n] *= a;
                    h[n] = fmaf(a, h[n], s*sB[t][n]);
                }
            }
        }
    }
    if (fast) {
        float pw = Pp;
        #pragma unroll
        for (int n=0;n<DS;n++) { ap[n] = pw; pw *= Pp; }
    }
    #pragma unroll
    for (int n=0;n<DS;n++) {
        E[(g*DS+n)*NCHAIN + chain] = h[n];
        P[(g*DS+n)*NCHAIN + chain] = ap[n];
    }
}

__global__ void scan_phaseB(const float* __restrict__ E,
                            const float* __restrict__ P,
                            float* __restrict__ Hi)
{
    int c = blockIdx.x*256 + threadIdx.x;
    if (c >= NCHAIN) return;
    #pragma unroll
    for (int n=0;n<DS;n++) {
        float carry = 0.f;
        #pragma unroll
        for (int g=0;g<NCHUNK;g++) {
            int o = (g*DS+n)*NCHAIN + c;
            Hi[o] = carry;
            carry = fmaf(P[o], carry, E[o]);
        }
    }
}

__global__ void scan_phaseC(const float* __restrict__ dt,
                            const float* __restrict__ u,
                            const float* __restrict__ xdbl,
                            const float* __restrict__ xz,
                            const float* __restrict__ Alog,
                            const float* __restrict__ Dpar,
                            const float* __restrict__ Hi,
                            float* __restrict__ yout)
{
    const int d = blockIdx.x*128 + threadIdx.x;
    const int g = blockIdx.y;
    const int b = blockIdx.z;
    const int chain = b*DI + d;

    float A[DS];
    #pragma unroll
    for (int n=0;n<DS;n++) A[n] = -expf(Alog[d*DS+n]);
    bool fast = true;
    #pragma unroll
    for (int n=1;n<DS;n++)
        fast = fast && (fabsf(A[n] - A[0]*(float)(n+1)) <= 1e-4f*fabsf(A[n]) + 1e-6f);

    float h[DS];
    #pragma unroll
    for (int n=0;n<DS;n++) h[n] = Hi[(g*DS+n)*NCHAIN + chain];
    const float Dp = Dpar[d];

    __shared__ float sBC[16][2*DS];
    const int bl0 = b*LL + g*CLEN;

    for (int t0=0; t0<CLEN; t0+=16) {
        __syncthreads();
        for (int q=threadIdx.x; q<16*2*DS; q+=128) {
            int j = q >> 5, m = q & 31;
            sBC[j][m] = xdbl[(bl0+t0+j)*XDW + DTR + m];
        }
        __syncthreads();
        for (int t=0;t<16;t++) {
            int idx = bl0 + t0 + t;
            float ld = dt[idx*DI + d];
            float lu = u [idx*DI + d];
            float s  = ld * lu;
            float y  = 0.f;
            if (fast) {
                float p = __expf(ld*A[0]);
                float pw = p;
                #pragma unroll
                for (int n=0;n<DS;n++) {
                    h[n] = fmaf(pw, h[n], s*sBC[t][n]);
                    y    = fmaf(h[n], sBC[t][DS+n], y);
                    pw *= p;
                }
            } else {
                #pragma unroll
                for (int n=0;n<DS;n++) {
                    float a = __expf(ld*A[n]);
                    h[n] = fmaf(a, h[n], s*sBC[t][n]);
                    y    = fmaf(h[n], sBC[t][DS+n], y);
                }
            }
            float z   = xz[(size_t)idx*(2*DI) + DI + d];
            float sig = 1.f / (1.f + __expf(-z));
            yout[idx*DI + d] = (y + lu*Dp) * z * sig;
        }
    }
}

// ---------------------------------------------------------------------------
// Head
// ---------------------------------------------------------------------------
__global__ void head_kernel(const float* __restrict__ x,
                            const int* __restrict__ lens,
                            const float* __restrict__ W1,
                            const float* __restrict__ b1,
                            const float* __restrict__ W2,
                            const float* __restrict__ b2,
                            float* __restrict__ out)
{
    __shared__ float xs[DM];
    __shared__ float red[DHID];
    const int b = blockIdx.x;
    const int tid = threadIdx.x;
    const int l = lens[b] - 1;
    const float* xr = x + ((size_t)(b*LL + l))*DM;
    for (int i=tid; i<DM; i+=DHID) xs[i] = xr[i];
    __syncthreads();
    float acc = b1[tid];
    const float* w = W1 + tid*DM;
    #pragma unroll 4
    for (int d0=0; d0<DM; d0+=4) {
        float4 wv = *(const float4*)(w + d0);
        acc = fmaf(wv.x, xs[d0+0], acc);
        acc = fmaf(wv.y, xs[d0+1], acc);
        acc = fmaf(wv.z, xs[d0+2], acc);
        acc = fmaf(wv.w, xs[d0+3], acc);
    }
    float hh = fmaxf(acc, 0.f);
    red[tid] = hh * W2[tid];
    __syncthreads();
    for (int s=DHID/2; s>0; s>>=1) {
        if (tid < s) red[tid] += red[tid+s];
        __syncthreads();
    }
    if (tid == 0) out[b] = red[0] + b2[0];
}

// ---------------------------------------------------------------------------
// Host launcher
// ---------------------------------------------------------------------------
extern "C" void kernel_launch(void* const* d_in, const int* in_sizes, int n_in,
                              void* d_out, int out_size)
{
    const int*   rna     = (const int*)  d_in[0];
    const int*   tissue  = (const int*)  d_in[1];
    const int*   lens    = (const int*)  d_in[2];
    const float* seq_emb = (const float*)d_in[3];
    const float* tis_emb = (const float*)d_in[4];
    const float* W_in    = (const float*)d_in[5];
    const float* conv_w  = (const float*)d_in[6];
    const float* conv_b  = (const float*)d_in[7];
    const float* W_xp    = (const float*)d_in[8];
    const float* W_dt    = (const float*)d_in[9];
    const float* b_dt    = (const float*)d_in[10];
    const float* A_log   = (const float*)d_in[11];
    const float* D_par   = (const float*)d_in[12];
    const float* W_out   = (const float*)d_in[13];
    const float* W1      = (const float*)d_in[14];
    const float* b1      = (const float*)d_in[15];
    const float* W2      = (const float*)d_in[16];
    const float* b2      = (const float*)d_in[17];

    float *px0, *px1, *pxz, *pu, *pxd, *pdt, *py, *pE, *pP, *pHi;
    cudaGetSymbolAddress((void**)&px0, g_x0);
    cudaGetSymbolAddress((void**)&px1, g_x1);
    cudaGetSymbolAddress((void**)&pxz, g_xz);
    cudaGetSymbolAddress((void**)&pu,  g_u);
    cudaGetSymbolAddress((void**)&pxd, g_xdbl);
    cudaGetSymbolAddress((void**)&pdt, g_dt);
    cudaGetSymbolAddress((void**)&py,  g_y);
    cudaGetSymbolAddress((void**)&pE,  g_E);
    cudaGetSymbolAddress((void**)&pP,  g_P);
    cudaGetSymbolAddress((void**)&pHi, g_Hi);

    cudaFuncSetAttribute(gemm_tf32,
                         cudaFuncAttributeMaxDynamicSharedMemorySize, TF_SMEM);

    embed_kernel<<<(BLTOT*DM+255)/256, 256>>>(rna, tissue, seq_emb, tis_emb, px0);

    float* xin  = px0;
    float* xout = px1;
    for (int i=0; i<NL; i++) {
        // in-proj: [16384,512] x [2048,512]^T -> xz  (TF32 TC, 2048 blocks)
        gemm_tf32<<<dim3((2*DI)/TF_BN, BLTOT/TF_BM), TF_NT, TF_SMEM>>>(
            xin, DM, W_in + (size_t)i*2*DI*DM, DM, pxz, 2*DI, DM);
        // conv + silu -> u
        conv_silu_kernel<<<(BLTOT*DI+255)/256, 256>>>(
            pxz, conv_w + i*DI*DCONV, conv_b + i*DI, pu);
        // x-proj: [16384,1024] x [64,1024]^T -> xdbl  (fp32 SIMT, 256 blocks)
        gemm_nt<64,64,16,4,4,0><<<dim3(XDW/64, BLTOT/64), 256>>>(
            pu, DI, W_xp + (size_t)i*XDW*DI, DI, pxd, XDW, DI, nullptr);
        // dt: softplus([16384,32] x [1024,32]^T + b_dt)  (fp32 SIMT, 2048 blocks)
        gemm_nt<64,128,16,4,8,1><<<dim3(DI/128, BLTOT/64), 256>>>(
            pxd, XDW, W_dt + (size_t)i*DI*DTR, DTR, pdt, DI, DTR, b_dt + i*DI);
        // selective scan (32 chunks)
        scan_phaseA<<<dim3(DI/128, NCHUNK, BB), 128>>>(
            pdt, pu, pxd, A_log + (size_t)i*DI*DS, pE, pP);
        scan_phaseB<<<(NCHAIN+255)/256, 256>>>(pE, pP, pHi);
        scan_phaseC<<<dim3(DI/128, NCHUNK, BB), 128>>>(
            pdt, pu, pxd, pxz, A_log + (size_t)i*DI*DS, D_par + i*DI, pHi, py);
        // out-proj: [16384,1024] x [512,1024]^T -> x_next  (TF32 TC)
        gemm_tf32<<<dim3(DM/TF_BN, BLTOT/TF_BM), TF_NT, TF_SMEM>>>(
            py, DI, W_out + (size_t)i*DM*DI, DI, xout, DM, DI);

        float* tmp = xin; xin = xout; xout = tmp;
    }

    head_kernel<<<BB, DHID>>>(xin, lens, W1, b1, W2, b2, (float*)d_out);
}

// round 7
// speedup vs baseline: 1.3523x; 1.0142x over previous
#include <cuda_runtime.h>
#include <cuda_bf16.h>
#include <cstdint>
#include <math.h>
#include <mma.h>

using namespace nvcuda;

// ---------------------------------------------------------------------------
// Model constants
// ---------------------------------------------------------------------------
#define BB       8
#define LL       2048
#define BLTOT    (BB*LL)        // 16384
#define DM       512
#define DI       1024           // d_inner
#define DS       16             // d_state
#define DTR      32             // dt_rank
#define XDW      64             // dt_rank + 2*d_state
#define NL       4
#define DCONV    4
#define DHID     256
// scan chunking
#define NCHUNK   32
#define CLEN     (LL/NCHUNK)    // 64
#define NCHAIN   (BB*DI)        // 8192

// ---------------------------------------------------------------------------
// Scratch (device globals; allocation APIs are forbidden)
// ---------------------------------------------------------------------------
__device__ float g_x0  [BLTOT*DM];
__device__ float g_x1  [BLTOT*DM];
__device__ float g_xz  [(size_t)BLTOT*2*DI];
__device__ float g_u   [BLTOT*DI];
__device__ float g_xdbl[BLTOT*XDW];
__device__ float g_y   [BLTOT*DI];
__device__ float g_E   [NCHUNK*DS*NCHAIN];
__device__ float g_P   [NCHUNK*DS*NCHAIN];
__device__ float g_Hi  [NCHUNK*DS*NCHAIN];

// ---------------------------------------------------------------------------
// FMA-only transcendentals (no MUFU): exp, log, sigmoid, softplus
// ---------------------------------------------------------------------------
__device__ __forceinline__ float fexp(float x)
{
    x = fminf(fmaxf(x, -87.0f), 87.0f);
    float t = x * 1.4426950408889634f;             // x * log2(e)
    float z = t + 12582912.0f;                      // round to nearest int
    int   ir = __float_as_int(z) - 0x4B400000;
    float r = z - 12582912.0f;
    float f = t - r;                                // f in [-0.5, 0.5]
    float p =            1.535336188319500e-4f;
    p = fmaf(p, f, 1.339887440266574e-3f);
    p = fmaf(p, f, 9.618437357674640e-3f);
    p = fmaf(p, f, 5.550332471162809e-2f);
    p = fmaf(p, f, 2.402264791363012e-1f);
    p = fmaf(p, f, 6.931472028550421e-1f);
    p = fmaf(p, f, 1.0f);
    return p * __int_as_float((ir + 127) << 23);    // * 2^ir
}

__device__ __forceinline__ float flog(float y)      // y > 0
{
    int i = __float_as_int(y);
    int e = (i - 0x3f3504f3) >> 23;
    float m = __int_as_float(i - (e << 23));        // [0.7071, 1.4142)
    float f = m - 1.0f;
    float zz = f * f;
    float p =            7.0376836292e-2f;
    p = fmaf(p, f, -1.1514610310e-1f);
    p = fmaf(p, f,  1.1676998740e-1f);
    p = fmaf(p, f, -1.2420140846e-1f);
    p = fmaf(p, f,  1.4249322787e-1f);
    p = fmaf(p, f, -1.6668057665e-1f);
    p = fmaf(p, f,  2.0000714765e-1f);
    p = fmaf(p, f, -2.4999993993e-1f);
    p = fmaf(p, f,  3.3333331174e-1f);
    float r = p * (f * zz);
    r = fmaf(-0.5f, zz, r);
    r = r + f;
    r = fmaf((float)e, 0.69314718055994531f, r);
    return r;
}

__device__ __forceinline__ float fsigmoid(float x)
{
    float e = fexp(-fabsf(x));
    float d = 1.0f + e;                 // (1, 2]
    float r = fmaf(-0.5f, d, 1.457107f);     // linear seed for 1/d on [1,2]
    r = r * fmaf(-d, r, 2.0f);               // Newton x3
    r = r * fmaf(-d, r, 2.0f);
    r = r * fmaf(-d, r, 2.0f);
    return x >= 0.f ? r : 1.0f - r;
}

__device__ __forceinline__ float fsoftplus(float v)
{
    return flog(1.0f + fexp(v));
}

// ---------------------------------------------------------------------------
// Embedding
// ---------------------------------------------------------------------------
__global__ void embed_kernel(const int* __restrict__ rna,
                             const int* __restrict__ tissue,
                             const float* __restrict__ seq_emb,
                             const float* __restrict__ tis_emb,
                             float* __restrict__ x)
{
    int i = blockIdx.x*256 + threadIdx.x;
    if (i >= BLTOT*DM) return;
    int d  = i & (DM-1);
    int bl = i >> 9;
    int b  = bl >> 11;
    int tok = rna[bl];
    float v = 0.f;
    if (tok != 0)
        v = seq_emb[tok*DM + d] + tis_emb[tissue[b]*DM + d];
    x[i] = v;
}

// ---------------------------------------------------------------------------
// TF32 tensor-core GEMM: C[M,N] = A[M,K] * W[N,K]^T (row-major, K contig)
// 4 warps, 64x64 warp tiles, 3-stage cp.async pipeline, 128x128x32 block tile.
// ---------------------------------------------------------------------------
#define TF_BM 128
#define TF_BN 128
#define TF_BK 32
#define TF_WM 64
#define TF_WN 64
#define TF_NT 128
#define TF_LDSH (TF_BK+4)
#define TF_STG 3
#define TF_ABUF (TF_BM*TF_LDSH)
#define TF_BBUF (TF_BN*TF_LDSH)
#define TF_SMEM (TF_STG*(TF_ABUF+TF_BBUF)*4)

__global__ __launch_bounds__(TF_NT)
void gemm_tf32(const float* __restrict__ A, int lda,
               const float* __restrict__ W, int ldb,
               float* __restrict__ C, int ldc, int K)
{
    extern __shared__ float smem[];
    float* As = smem;
    float* Bs = smem + TF_STG*TF_ABUF;

    const int tid = threadIdx.x;
    const int wid = tid >> 5;
    const int wr  = wid >> 1;
    const int wc  = wid & 1;
    const int m0  = blockIdx.y*TF_BM;
    const int n0  = blockIdx.x*TF_BN;

    constexpr int TM = TF_WM/16, TN = TF_WN/16;
    wmma::fragment<wmma::accumulator,16,16,8,float> acc[TM][TN];
    #pragma unroll
    for (int i=0;i<TM;i++)
        #pragma unroll
        for (int j=0;j<TN;j++) wmma::fill_fragment(acc[i][j], 0.f);

    constexpr int AIT = (TF_BM*TF_BK)/(4*TF_NT);
    constexpr int BIT = (TF_BN*TF_BK)/(4*TF_NT);

    auto issue = [&](int kt, int buf){
        int k0 = kt*TF_BK;
        float* as = As + buf*TF_ABUF;
        float* bs = Bs + buf*TF_BBUF;
        #pragma unroll
        for (int i=0;i<AIT;i++){
            int q = tid + i*TF_NT;
            int r = q >> 3; int c = (q & 7)*4;
            unsigned int d = (unsigned int)__cvta_generic_to_shared(as + r*TF_LDSH + c);
            const float* s = A + (size_t)(m0+r)*lda + k0 + c;
            asm volatile("cp.async.cg.shared.global [%0],[%1],16;\n" :: "r"(d), "l"(s));
        }
        #pragma unroll
        for (int i=0;i<BIT;i++){
            int q = tid + i*TF_NT;
            int r = q >> 3; int c = (q & 7)*4;
            unsigned int d = (unsigned int)__cvta_generic_to_shared(bs + r*TF_LDSH + c);
            const float* s = W + (size_t)(n0+r)*ldb + k0 + c;
            asm volatile("cp.async.cg.shared.global [%0],[%1],16;\n" :: "r"(d), "l"(s));
        }
        asm volatile("cp.async.commit_group;\n");
    };

    const int KT = K/TF_BK;
    issue(0, 0);
    if (KT > 1) issue(1, 1);

    for (int kt=0; kt<KT; kt++){
        if (kt+2 < KT) {
            issue(kt+2, (kt+2)%TF_STG);
            asm volatile("cp.async.wait_group 2;\n");
        } else if (kt+1 < KT) {
            asm volatile("cp.async.wait_group 1;\n");
        } else {
            asm volatile("cp.async.wait_group 0;\n");
        }
        __syncthreads();

        const float* as = As + (kt%TF_STG)*TF_ABUF;
        const float* bs = Bs + (kt%TF_STG)*TF_BBUF;
        #pragma unroll
        for (int kk=0; kk<TF_BK/8; kk++){
            wmma::fragment<wmma::matrix_a,16,16,8,wmma::precision::tf32,wmma::row_major> af[TM];
            wmma::fragment<wmma::matrix_b,16,16,8,wmma::precision::tf32,wmma::col_major> bf[TN];
            #pragma unroll
            for (int i=0;i<TM;i++){
                wmma::load_matrix_sync(af[i], as + (wr*TF_WM + i*16)*TF_LDSH + kk*8, TF_LDSH);
                #pragma unroll
                for (int t=0;t<af[i].num_elements;t++)
                    af[i].x[t] = wmma::__float_to_tf32(af[i].x[t]);
            }
            #pragma unroll
            for (int j=0;j<TN;j++){
                wmma::load_matrix_sync(bf[j], bs + (wc*TF_WN + j*16)*TF_LDSH + kk*8, TF_LDSH);
                #pragma unroll
                for (int t=0;t<bf[j].num_elements;t++)
                    bf[j].x[t] = wmma::__float_to_tf32(bf[j].x[t]);
            }
            #pragma unroll
            for (int i=0;i<TM;i++)
                #pragma unroll
                for (int j=0;j<TN;j++)
                    wmma::mma_sync(acc[i][j], af[i], bf[j], acc[i][j]);
        }
        __syncthreads();
    }

    #pragma unroll
    for (int i=0;i<TM;i++)
        #pragma unroll
        for (int j=0;j<TN;j++){
            float* cp = C + (size_t)(m0 + wr*TF_WM + i*16)*ldc + n0 + wc*TF_WN + j*16;
            wmma::store_matrix_sync(cp, acc[i][j], ldc, wmma::mem_row_major);
        }
}

// ---------------------------------------------------------------------------
// SIMT fp32 GEMM (x-proj only now). NT = thread count.
// ---------------------------------------------------------------------------
template<int BM, int BN, int BK, int TM, int TN, int NT>
__global__ __launch_bounds__(NT)
void gemm_nt(const float* __restrict__ A, int lda,
             const float* __restrict__ W, int ldb,
             float* __restrict__ C, int ldc, int K)
{
    __shared__ float As[BK][BM];
    __shared__ float Bs[BK][BN];

    const int tid = threadIdx.x;
    const int m0 = blockIdx.y * BM;
    const int n0 = blockIdx.x * BN;
    constexpr int TCOLS = BN / TN;
    const int tm = tid / TCOLS;
    const int tn = tid % TCOLS;

    constexpr int AV = (BM*BK)/(4*NT);
    constexpr int BV = (BN*BK)/(4*NT);
    static_assert(AV >= 1 && BV >= 1, "tile too small");
    static_assert(NT*TM*TN == BM*BN, "thread/tile mismatch");

    float acc[TM][TN];
    #pragma unroll
    for (int i=0;i<TM;i++)
        #pragma unroll
        for (int j=0;j<TN;j++) acc[i][j] = 0.f;

    for (int k0 = 0; k0 < K; k0 += BK) {
        float4 av[AV], bv[BV];
        #pragma unroll
        for (int i=0;i<AV;i++) {
            int q  = tid + i*NT;
            int r  = q / (BK/4);
            int c4 = (q % (BK/4))*4;
            av[i] = *(const float4*)(A + (size_t)(m0+r)*lda + k0 + c4);
        }
        #pragma unroll
        for (int i=0;i<BV;i++) {
            int q  = tid + i*NT;
            int r  = q / (BK/4);
            int c4 = (q % (BK/4))*4;
            bv[i] = *(const float4*)(W + (size_t)(n0+r)*ldb + k0 + c4);
        }
        __syncthreads();
        #pragma unroll
        for (int i=0;i<AV;i++) {
            int q  = tid + i*NT;
            int r  = q / (BK/4);
            int c4 = (q % (BK/4))*4;
            As[c4+0][r]=av[i].x; As[c4+1][r]=av[i].y;
            As[c4+2][r]=av[i].z; As[c4+3][r]=av[i].w;
        }
        #pragma unroll
        for (int i=0;i<BV;i++) {
            int q  = tid + i*NT;
            int r  = q / (BK/4);
            int c4 = (q % (BK/4))*4;
            Bs[c4+0][r]=bv[i].x; Bs[c4+1][r]=bv[i].y;
            Bs[c4+2][r]=bv[i].z; Bs[c4+3][r]=bv[i].w;
        }
        __syncthreads();

        #pragma unroll
        for (int kk=0; kk<BK; kk++) {
            float a[TM], bb[TN];
            #pragma unroll
            for (int i=0;i<TM;i+=4)
                *(float4*)&a[i] = *(const float4*)&As[kk][tm*TM+i];
            #pragma unroll
            for (int j=0;j<TN;j+=4)
                *(float4*)&bb[j] = *(const float4*)&Bs[kk][tn*TN+j];
            #pragma unroll
            for (int i=0;i<TM;i++)
                #pragma unroll
                for (int j=0;j<TN;j++)
                    acc[i][j] = fmaf(a[i], bb[j], acc[i][j]);
        }
    }

    #pragma unroll
    for (int i=0;i<TM;i++) {
        int row = m0 + tm*TM + i;
        #pragma unroll
        for (int j=0;j<TN;j++) {
            int col = n0 + tn*TN + j;
            C[(size_t)row*ldc + col] = acc[i][j];
        }
    }
}

// ---------------------------------------------------------------------------
// Causal depthwise conv (k=4) + bias + SiLU (FMA-only sigmoid)
// ---------------------------------------------------------------------------
__global__ void conv_silu_kernel(const float* __restrict__ xz,
                                 const float* __restrict__ cw,
                                 const float* __restrict__ cb,
                                 float* __restrict__ u)
{
    int i = blockIdx.x*256 + threadIdx.x;
    if (i >= BLTOT*DI) return;
    int c  = i & (DI-1);
    int bl = i >> 10;
    int l  = bl & (LL-1);
    int b  = bl >> 11;
    float acc = cb[c];
    #pragma unroll
    for (int k=0;k<DCONV;k++) {
        int ll = l + k - (DCONV-1);
        if (ll >= 0)
            acc = fmaf(xz[((size_t)((b<<11)+ll))*(2*DI) + c], cw[c*DCONV+k], acc);
    }
    u[i] = acc * fsigmoid(acc);
}

// ---------------------------------------------------------------------------
// Selective scan, chunked two-pass, with dt-GEMM fused in (Wdt row in regs).
// ---------------------------------------------------------------------------
__global__ __launch_bounds__(128)
void scan_phaseA(const float* __restrict__ u,
                 const float* __restrict__ xdbl,
                 const float* __restrict__ Wdt,
                 const float* __restrict__ bdt,
                 const float* __restrict__ Alog,
                 float* __restrict__ E,
                 float* __restrict__ P)
{
    const int d = blockIdx.x*128 + threadIdx.x;
    const int g = blockIdx.y;
    const int b = blockIdx.z;
    const int chain = b*DI + d;

    __shared__ float sW[128*33];
    __shared__ float sX[16][XDW];

    // stage this block's Wdt rows (coalesced), then copy own row to regs
    {
        const float* wsrc = Wdt + (size_t)(blockIdx.x*128)*DTR;
        for (int idx = threadIdx.x; idx < 128*DTR; idx += 128) {
            int j = idx >> 5, r = idx & 31;
            sW[j*33 + r] = wsrc[idx];
        }
    }
    __syncthreads();
    float Wr[DTR];
    #pragma unroll
    for (int r=0;r<DTR;r++) Wr[r] = sW[threadIdx.x*33 + r];
    const float bd = bdt[d];

    float A[DS];
    #pragma unroll
    for (int n=0;n<DS;n++) A[n] = -fexp(Alog[d*DS+n]);
    bool fast = true;
    #pragma unroll
    for (int n=1;n<DS;n++)
        fast = fast && (fabsf(A[n] - A[0]*(float)(n+1)) <= 1e-4f*fabsf(A[n]) + 1e-6f);

    float h[DS], ap[DS];
    #pragma unroll
    for (int n=0;n<DS;n++) { h[n]=0.f; ap[n]=1.f; }
    float Pp = 1.f;

    const int bl0 = b*LL + g*CLEN;

    for (int t0=0; t0<CLEN; t0+=16) {
        __syncthreads();
        for (int q=threadIdx.x; q<16*XDW; q+=128) {
            int j = q >> 6, m = q & 63;
            sX[j][m] = xdbl[(bl0+t0+j)*XDW + m];
        }
        __syncthreads();
        for (int t=0;t<16;t++) {
            int idx = bl0 + t0 + t;
            float v = bd;
            #pragma unroll
            for (int r=0;r<DTR;r++) v = fmaf(sX[t][r], Wr[r], v);
            float ldt = fsoftplus(v);
            float s   = ldt * u[idx*DI + d];
            if (fast) {
                float p = fexp(ldt*A[0]);
                Pp *= p;
                float pw = p;
                #pragma unroll
                for (int n=0;n<DS;n++) { h[n] = fmaf(pw, h[n], s*sX[t][DTR+n]); pw *= p; }
            } else {
                #pragma unroll
                for (int n=0;n<DS;n++) {
                    float a = fexp(ldt*A[n]);
                    ap[n] *= a;
                    h[n] = fmaf(a, h[n], s*sX[t][DTR+n]);
                }
            }
        }
    }
    if (fast) {
        float pw = Pp;
        #pragma unroll
        for (int n=0;n<DS;n++) { ap[n] = pw; pw *= Pp; }
    }
    #pragma unroll
    for (int n=0;n<DS;n++) {
        E[(g*DS+n)*NCHAIN + chain] = h[n];
        P[(g*DS+n)*NCHAIN + chain] = ap[n];
    }
}

__global__ void scan_phaseB(const float* __restrict__ E,
                            const float* __restrict__ P,
                            float* __restrict__ Hi)
{
    int c = blockIdx.x*256 + threadIdx.x;
    if (c >= NCHAIN) return;
    #pragma unroll
    for (int n=0;n<DS;n++) {
        float carry = 0.f;
        #pragma unroll
        for (int g=0;g<NCHUNK;g++) {
            int o = (g*DS+n)*NCHAIN + c;
            Hi[o] = carry;
            carry = fmaf(P[o], carry, E[o]);
        }
    }
}

__global__ __launch_bounds__(128)
void scan_phaseC(const float* __restrict__ u,
                 const float* __restrict__ xdbl,
                 const float* __restrict__ xz,
                 const float* __restrict__ Wdt,
                 const float* __restrict__ bdt,
                 const float* __restrict__ Alog,
                 const float* __restrict__ Dpar,
                 const float* __restrict__ Hi,
                 float* __restrict__ yout)
{
    const int d = blockIdx.x*128 + threadIdx.x;
    const int g = blockIdx.y;
    const int b = blockIdx.z;
    const int chain = b*DI + d;

    __shared__ float sW[128*33];
    __shared__ float sX[16][XDW];

    {
        const float* wsrc = Wdt + (size_t)(blockIdx.x*128)*DTR;
        for (int idx = threadIdx.x; idx < 128*DTR; idx += 128) {
            int j = idx >> 5, r = idx & 31;
            sW[j*33 + r] = wsrc[idx];
        }
    }
    __syncthreads();
    float Wr[DTR];
    #pragma unroll
    for (int r=0;r<DTR;r++) Wr[r] = sW[threadIdx.x*33 + r];
    const float bd = bdt[d];

    float A[DS];
    #pragma unroll
    for (int n=0;n<DS;n++) A[n] = -fexp(Alog[d*DS+n]);
    bool fast = true;
    #pragma unroll
    for (int n=1;n<DS;n++)
        fast = fast && (fabsf(A[n] - A[0]*(float)(n+1)) <= 1e-4f*fabsf(A[n]) + 1e-6f);

    float h[DS];
    #pragma unroll
    for (int n=0;n<DS;n++) h[n] = Hi[(g*DS+n)*NCHAIN + chain];
    const float Dp = Dpar[d];

    const int bl0 = b*LL + g*CLEN;

    for (int t0=0; t0<CLEN; t0+=16) {
        __syncthreads();
        for (int q=threadIdx.x; q<16*XDW; q+=128) {
            int j = q >> 6, m = q & 63;
            sX[j][m] = xdbl[(bl0+t0+j)*XDW + m];
        }
        __syncthreads();
        for (int t=0;t<16;t++) {
            int idx = bl0 + t0 + t;
            float v = bd;
            #pragma unroll
            for (int r=0;r<DTR;r++) v = fmaf(sX[t][r], Wr[r], v);
            float ldt = fsoftplus(v);
            float lu  = u[idx*DI + d];
            float s   = ldt * lu;
            float y   = 0.f;
            if (fast) {
                float p = fexp(ldt*A[0]);
                float pw = p;
                #pragma unroll
                for (int n=0;n<DS;n++) {
                    h[n] = fmaf(pw, h[n], s*sX[t][DTR+n]);
                    y    = fmaf(h[n], sX[t][DTR+DS+n], y);
                    pw *= p;
                }
            } else {
                #pragma unroll
                for (int n=0;n<DS;n++) {
                    float a = fexp(ldt*A[n]);
                    h[n] = fmaf(a, h[n], s*sX[t][DTR+n]);
                    y    = fmaf(h[n], sX[t][DTR+DS+n], y);
                }
            }
            float z = xz[(size_t)idx*(2*DI) + DI + d];
            yout[idx*DI + d] = (y + lu*Dp) * z * fsigmoid(z);
        }
    }
}

// ---------------------------------------------------------------------------
// Head
// ---------------------------------------------------------------------------
__global__ void head_kernel(const float* __restrict__ x,
                            const int* __restrict__ lens,
                            const float* __restrict__ W1,
                            const float* __restrict__ b1,
                            const float* __restrict__ W2,
                            const float* __restrict__ b2,
                            float* __restrict__ out)
{
    __shared__ float xs[DM];
    __shared__ float red[DHID];
    const int b = blockIdx.x;
    const int tid = threadIdx.x;
    const int l = lens[b] - 1;
    const float* xr = x + ((size_t)(b*LL + l))*DM;
    for (int i=tid; i<DM; i+=DHID) xs[i] = xr[i];
    __syncthreads();
    float acc = b1[tid];
    const float* w = W1 + tid*DM;
    #pragma unroll 4
    for (int d0=0; d0<DM; d0+=4) {
        float4 wv = *(const float4*)(w + d0);
        acc = fmaf(wv.x, xs[d0+0], acc);
        acc = fmaf(wv.y, xs[d0+1], acc);
        acc = fmaf(wv.z, xs[d0+2], acc);
        acc = fmaf(wv.w, xs[d0+3], acc);
    }
    float hh = fmaxf(acc, 0.f);
    red[tid] = hh * W2[tid];
    __syncthreads();
    for (int s=DHID/2; s>0; s>>=1) {
        if (tid < s) red[tid] += red[tid+s];
        __syncthreads();
    }
    if (tid == 0) out[b] = red[0] + b2[0];
}

// ---------------------------------------------------------------------------
// Host launcher
// ---------------------------------------------------------------------------
extern "C" void kernel_launch(void* const* d_in, const int* in_sizes, int n_in,
                              void* d_out, int out_size)
{
    const int*   rna     = (const int*)  d_in[0];
    const int*   tissue  = (const int*)  d_in[1];
    const int*   lens    = (const int*)  d_in[2];
    const float* seq_emb = (const float*)d_in[3];
    const float* tis_emb = (const float*)d_in[4];
    const float* W_in    = (const float*)d_in[5];
    const float* conv_w  = (const float*)d_in[6];
    const float* conv_b  = (const float*)d_in[7];
    const float* W_xp    = (const float*)d_in[8];
    const float* W_dt    = (const float*)d_in[9];
    const float* b_dt    = (const float*)d_in[10];
    const float* A_log   = (const float*)d_in[11];
    const float* D_par   = (const float*)d_in[12];
    const float* W_out   = (const float*)d_in[13];
    const float* W1      = (const float*)d_in[14];
    const float* b1      = (const float*)d_in[15];
    const float* W2      = (const float*)d_in[16];
    const float* b2      = (const float*)d_in[17];

    float *px0, *px1, *pxz, *pu, *pxd, *py, *pE, *pP, *pHi;
    cudaGetSymbolAddress((void**)&px0, g_x0);
    cudaGetSymbolAddress((void**)&px1, g_x1);
    cudaGetSymbolAddress((void**)&pxz, g_xz);
    cudaGetSymbolAddress((void**)&pu,  g_u);
    cudaGetSymbolAddress((void**)&pxd, g_xdbl);
    cudaGetSymbolAddress((void**)&py,  g_y);
    cudaGetSymbolAddress((void**)&pE,  g_E);
    cudaGetSymbolAddress((void**)&pP,  g_P);
    cudaGetSymbolAddress((void**)&pHi, g_Hi);

    cudaFuncSetAttribute(gemm_tf32,
                         cudaFuncAttributeMaxDynamicSharedMemorySize, TF_SMEM);

    embed_kernel<<<(BLTOT*DM+255)/256, 256>>>(rna, tissue, seq_emb, tis_emb, px0);

    float* xin  = px0;
    float* xout = px1;
    for (int i=0; i<NL; i++) {
        // in-proj: [16384,512] x [2048,512]^T -> xz  (TF32 TC)
        gemm_tf32<<<dim3((2*DI)/TF_BN, BLTOT/TF_BM), TF_NT, TF_SMEM>>>(
            xin, DM, W_in + (size_t)i*2*DI*DM, DM, pxz, 2*DI, DM);
        // conv + silu -> u
        conv_silu_kernel<<<(BLTOT*DI+255)/256, 256>>>(
            pxz, conv_w + i*DI*DCONV, conv_b + i*DI, pu);
        // x-proj: [16384,1024] x [64,1024]^T -> xdbl  (fp32 SIMT, 512 blocks)
        gemm_nt<32,64,16,4,4,128><<<dim3(XDW/64, BLTOT/32), 128>>>(
            pu, DI, W_xp + (size_t)i*XDW*DI, DI, pxd, XDW, DI);
        // selective scan (dt fused)
        scan_phaseA<<<dim3(DI/128, NCHUNK, BB), 128>>>(
            pu, pxd, W_dt + (size_t)i*DI*DTR, b_dt + i*DI,
            A_log + (size_t)i*DI*DS, pE, pP);
        scan_phaseB<<<(NCHAIN+255)/256, 256>>>(pE, pP, pHi);
        scan_phaseC<<<dim3(DI/128, NCHUNK, BB), 128>>>(
            pu, pxd, pxz, W_dt + (size_t)i*DI*DTR, b_dt + i*DI,
            A_log + (size_t)i*DI*DS, D_par + i*DI, pHi, py);
        // out-proj: [16384,1024] x [512,1024]^T -> x_next  (TF32 TC)
        gemm_tf32<<<dim3(DM/TF_BN, BLTOT/TF_BM), TF_NT, TF_SMEM>>>(
            py, DI, W_out + (size_t)i*DM*DI, DI, xout, DM, DI);

        float* tmp = xin; xin = xout; xout = tmp;
    }

    head_kernel<<<BB, DHID>>>(xin, lens, W1, b1, W2, b2, (float*)d_out);
}

// round 8
// speedup vs baseline: 2.6200x; 1.9375x over previous
#include <cuda_runtime.h>
#include <cuda_fp16.h>
#include <cstdint>
#include <math.h>
#include <mma.h>

using namespace nvcuda;

// ---------------------------------------------------------------------------
// Model constants
// ---------------------------------------------------------------------------
#define BB       8
#define LL       2048
#define BLTOT    (BB*LL)        // 16384
#define DM       512
#define DI       1024           // d_inner
#define DS       16             // d_state
#define DTR      32             // dt_rank
#define XDW      64             // dt_rank + 2*d_state
#define NL       4
#define DCONV    4
#define DHID     256
// scan chunking
#define NCHUNK   32
#define CLEN     (LL/NCHUNK)    // 64
#define NCHAIN   (BB*DI)        // 8192

// ---------------------------------------------------------------------------
// Scratch (device globals; allocation APIs are forbidden)
// ---------------------------------------------------------------------------
__device__ __half g_x0  [BLTOT*DM];
__device__ __half g_x1  [BLTOT*DM];
__device__ __half g_xz  [(size_t)BLTOT*2*DI];
__device__ __half g_u   [BLTOT*DI];
__device__ float  g_xdbl[BLTOT*XDW];
__device__ __half g_y   [BLTOT*DI];
__device__ float  g_E   [NCHUNK*DS*NCHAIN];
__device__ float  g_P   [NCHUNK*DS*NCHAIN];
__device__ float  g_Hi  [NCHUNK*DS*NCHAIN];
// fp16 weight copies (converted once per launch)
__device__ __half g_Whin [NL*2*DI*DM];
__device__ __half g_Whxp [NL*XDW*DI];
__device__ __half g_Whout[NL*DM*DI];

// ---------------------------------------------------------------------------
// FMA-only transcendentals
// ---------------------------------------------------------------------------
__device__ __forceinline__ float fexp(float x)
{
    x = fminf(fmaxf(x, -87.0f), 87.0f);
    float t = x * 1.4426950408889634f;
    float z = t + 12582912.0f;
    int   ir = __float_as_int(z) - 0x4B400000;
    float r = z - 12582912.0f;
    float f = t - r;
    float p =            1.535336188319500e-4f;
    p = fmaf(p, f, 1.339887440266574e-3f);
    p = fmaf(p, f, 9.618437357674640e-3f);
    p = fmaf(p, f, 5.550332471162809e-2f);
    p = fmaf(p, f, 2.402264791363012e-1f);
    p = fmaf(p, f, 6.931472028550421e-1f);
    p = fmaf(p, f, 1.0f);
    return p * __int_as_float((ir + 127) << 23);
}

__device__ __forceinline__ float flog(float y)
{
    int i = __float_as_int(y);
    int e = (i - 0x3f3504f3) >> 23;
    float m = __int_as_float(i - (e << 23));
    float f = m - 1.0f;
    float zz = f * f;
    float p =            7.0376836292e-2f;
    p = fmaf(p, f, -1.1514610310e-1f);
    p = fmaf(p, f,  1.1676998740e-1f);
    p = fmaf(p, f, -1.2420140846e-1f);
    p = fmaf(p, f,  1.4249322787e-1f);
    p = fmaf(p, f, -1.6668057665e-1f);
    p = fmaf(p, f,  2.0000714765e-1f);
    p = fmaf(p, f, -2.4999993993e-1f);
    p = fmaf(p, f,  3.3333331174e-1f);
    float r = p * (f * zz);
    r = fmaf(-0.5f, zz, r);
    r = r + f;
    r = fmaf((float)e, 0.69314718055994531f, r);
    return r;
}

__device__ __forceinline__ float fsigmoid(float x)
{
    float e = fexp(-fabsf(x));
    float d = 1.0f + e;
    float r = fmaf(-0.5f, d, 1.457107f);
    r = r * fmaf(-d, r, 2.0f);
    r = r * fmaf(-d, r, 2.0f);
    r = r * fmaf(-d, r, 2.0f);
    return x >= 0.f ? r : 1.0f - r;
}

__device__ __forceinline__ float fsoftplus(float v)
{
    return flog(1.0f + fexp(v));
}

// ---------------------------------------------------------------------------
// fp32 -> fp16 weight conversion
// ---------------------------------------------------------------------------
__global__ void cvt_kernel(const float* __restrict__ src, __half* __restrict__ dst, int n)
{
    int i = blockIdx.x*256 + threadIdx.x;
    if (i < n) dst[i] = __float2half(src[i]);
}

// ---------------------------------------------------------------------------
// Embedding (fp16 output)
// ---------------------------------------------------------------------------
__global__ void embed_kernel(const int* __restrict__ rna,
                             const int* __restrict__ tissue,
                             const float* __restrict__ seq_emb,
                             const float* __restrict__ tis_emb,
                             __half* __restrict__ x)
{
    int i = blockIdx.x*256 + threadIdx.x;
    if (i >= BLTOT*DM) return;
    int d  = i & (DM-1);
    int bl = i >> 9;
    int b  = bl >> 11;
    int tok = rna[bl];
    float v = 0.f;
    if (tok != 0)
        v = seq_emb[tok*DM + d] + tis_emb[tissue[b]*DM + d];
    x[i] = __float2half(v);
}

// ---------------------------------------------------------------------------
// fp16 tensor-core GEMM: C[M,N] = A[M,K] * W[N,K]^T
// A, W half row-major (K contiguous). CT = __half (smem-staged) or float.
// 3-stage cp.async pipeline; (BM/WM)x(BN/WN) warp grid of m16n16k16 frags.
// ---------------------------------------------------------------------------
template<int BM,int BN,int BK,int WM,int WN,int NT, typename CT>
__global__ __launch_bounds__(NT)
void gemm_h(const __half* __restrict__ A, int lda,
            const __half* __restrict__ W, int ldb,
            CT* __restrict__ C, int ldc, int K)
{
    constexpr bool HALF_OUT = (sizeof(CT) == 2);
    constexpr int LDSH = BK + 8;                 // half pitch; row bytes mult of 16
    constexpr int STG  = 3;
    constexpr int ABUF = BM*LDSH;                // halfs
    constexpr int BBUF = BN*LDSH;
    constexpr int WCOLS = BN/WN;
    constexpr int TM = WM/16, TN = WN/16;

    extern __shared__ __align__(16) unsigned char smem_raw[];
    __half* As = (__half*)smem_raw;
    __half* Bs = As + STG*ABUF;

    const int tid = threadIdx.x;
    const int wid = tid >> 5;
    const int wr  = wid / WCOLS;
    const int wc  = wid % WCOLS;
    const int m0  = blockIdx.y*BM;
    const int n0  = blockIdx.x*BN;

    wmma::fragment<wmma::accumulator,16,16,16,float> acc[TM][TN];
    #pragma unroll
    for (int i=0;i<TM;i++)
        #pragma unroll
        for (int j=0;j<TN;j++) wmma::fill_fragment(acc[i][j], 0.f);

    constexpr int AIT = (BM*BK)/(8*NT);          // 16B (8-half) chunks per thread
    constexpr int BIT = (BN*BK)/(8*NT);
    static_assert(AIT >= 1 && BIT >= 1, "tile/thread mismatch");

    auto issue = [&](int kt, int buf){
        int k0 = kt*BK;
        __half* as = As + buf*ABUF;
        __half* bs = Bs + buf*BBUF;
        #pragma unroll
        for (int i=0;i<AIT;i++){
            int q = tid + i*NT;
            int r = q / (BK/8); int c = (q % (BK/8))*8;
            unsigned int d = (unsigned int)__cvta_generic_to_shared(as + r*LDSH + c);
            const __half* s = A + (size_t)(m0+r)*lda + k0 + c;
            asm volatile("cp.async.cg.shared.global [%0],[%1],16;\n" :: "r"(d), "l"(s));
        }
        #pragma unroll
        for (int i=0;i<BIT;i++){
            int q = tid + i*NT;
            int r = q / (BK/8); int c = (q % (BK/8))*8;
            unsigned int d = (unsigned int)__cvta_generic_to_shared(bs + r*LDSH + c);
            const __half* s = W + (size_t)(n0+r)*ldb + k0 + c;
            asm volatile("cp.async.cg.shared.global [%0],[%1],16;\n" :: "r"(d), "l"(s));
        }
        asm volatile("cp.async.commit_group;\n");
    };

    const int KT = K/BK;
    issue(0, 0);
    if (KT > 1) issue(1, 1);

    for (int kt=0; kt<KT; kt++){
        if (kt+2 < KT) {
            issue(kt+2, (kt+2)%STG);
            asm volatile("cp.async.wait_group 2;\n");
        } else if (kt+1 < KT) {
            asm volatile("cp.async.wait_group 1;\n");
        } else {
            asm volatile("cp.async.wait_group 0;\n");
        }
        __syncthreads();

        const __half* as = As + (kt%STG)*ABUF;
        const __half* bs = Bs + (kt%STG)*BBUF;
        #pragma unroll
        for (int kk=0; kk<BK/16; kk++){
            wmma::fragment<wmma::matrix_a,16,16,16,__half,wmma::row_major> af[TM];
            wmma::fragment<wmma::matrix_b,16,16,16,__half,wmma::col_major> bf[TN];
            #pragma unroll
            for (int i=0;i<TM;i++)
                wmma::load_matrix_sync(af[i], as + (wr*WM + i*16)*LDSH + kk*16, LDSH);
            #pragma unroll
            for (int j=0;j<TN;j++)
                wmma::load_matrix_sync(bf[j], bs + (wc*WN + j*16)*LDSH + kk*16, LDSH);
            #pragma unroll
            for (int i=0;i<TM;i++)
                #pragma unroll
                for (int j=0;j<TN;j++)
                    wmma::mma_sync(acc[i][j], af[i], bf[j], acc[i][j]);
        }
        __syncthreads();
    }

    if (HALF_OUT) {
        // stage fp32 accum in smem (per-warp region), convert, write half2
        float* stage = (float*)smem_raw + wid*WM*WN;
        #pragma unroll
        for (int i=0;i<TM;i++)
            #pragma unroll
            for (int j=0;j<TN;j++)
                wmma::store_matrix_sync(stage + (i*16)*WN + j*16, acc[i][j], WN,
                                        wmma::mem_row_major);
        __syncwarp();
        __half* Cw = (__half*)C + (size_t)(m0 + wr*WM)*ldc + n0 + wc*WN;
        const int lane = tid & 31;
        #pragma unroll 4
        for (int q = lane; q < WM*WN/2; q += 32) {
            int row = q / (WN/2);
            int cc  = (q % (WN/2))*2;
            float2 v = *(float2*)(stage + row*WN + cc);
            *(__half2*)(Cw + (size_t)row*ldc + cc) = __floats2half2_rn(v.x, v.y);
        }
    } else {
        #pragma unroll
        for (int i=0;i<TM;i++)
            #pragma unroll
            for (int j=0;j<TN;j++){
                float* cp = (float*)C + (size_t)(m0 + wr*WM + i*16)*ldc + n0 + wc*WN + j*16;
                wmma::store_matrix_sync(cp, acc[i][j], ldc, wmma::mem_row_major);
            }
    }
}

// smem sizes (bytes)
#define GH_BIG_PIPE  (3*(128*(32+8) + 128*(32+8))*2)     // 61440
#define GH_BIG_STAGE (4*64*64*4)                          // 65536
#define GH_BIG_SMEM  (GH_BIG_STAGE > GH_BIG_PIPE ? GH_BIG_STAGE : GH_BIG_PIPE)
#define GH_XP_SMEM   (3*(64*(64+8) + 64*(64+8))*2)        // 55296

// ---------------------------------------------------------------------------
// Causal depthwise conv (k=4) + bias + SiLU (fp16 in/out, fp32 math)
// ---------------------------------------------------------------------------
__global__ void conv_silu_kernel(const __half* __restrict__ xz,
                                 const float* __restrict__ cw,
                                 const float* __restrict__ cb,
                                 __half* __restrict__ u)
{
    int i = blockIdx.x*256 + threadIdx.x;
    if (i >= BLTOT*DI) return;
    int c  = i & (DI-1);
    int bl = i >> 10;
    int l  = bl & (LL-1);
    int b  = bl >> 11;
    float acc = cb[c];
    #pragma unroll
    for (int k=0;k<DCONV;k++) {
        int ll = l + k - (DCONV-1);
        if (ll >= 0)
            acc = fmaf(__half2float(xz[((size_t)((b<<11)+ll))*(2*DI) + c]),
                       cw[c*DCONV+k], acc);
    }
    u[i] = __float2half(acc * fsigmoid(acc));
}

// ---------------------------------------------------------------------------
// Selective scan, chunked two-pass, dt-GEMM fused (Wdt row in regs)
// ---------------------------------------------------------------------------
__global__ __launch_bounds__(128)
void scan_phaseA(const __half* __restrict__ u,
                 const float* __restrict__ xdbl,
                 const float* __restrict__ Wdt,
                 const float* __restrict__ bdt,
                 const float* __restrict__ Alog,
                 float* __restrict__ E,
                 float* __restrict__ P)
{
    const int d = blockIdx.x*128 + threadIdx.x;
    const int g = blockIdx.y;
    const int b = blockIdx.z;
    const int chain = b*DI + d;

    __shared__ float sW[128*33];
    __shared__ float sX[16][XDW];

    {
        const float* wsrc = Wdt + (size_t)(blockIdx.x*128)*DTR;
        for (int idx = threadIdx.x; idx < 128*DTR; idx += 128) {
            int j = idx >> 5, r = idx & 31;
            sW[j*33 + r] = wsrc[idx];
        }
    }
    __syncthreads();
    float Wr[DTR];
    #pragma unroll
    for (int r=0;r<DTR;r++) Wr[r] = sW[threadIdx.x*33 + r];
    const float bd = bdt[d];

    float A[DS];
    #pragma unroll
    for (int n=0;n<DS;n++) A[n] = -fexp(Alog[d*DS+n]);
    bool fast = true;
    #pragma unroll
    for (int n=1;n<DS;n++)
        fast = fast && (fabsf(A[n] - A[0]*(float)(n+1)) <= 1e-4f*fabsf(A[n]) + 1e-6f);

    float h[DS], ap[DS];
    #pragma unroll
    for (int n=0;n<DS;n++) { h[n]=0.f; ap[n]=1.f; }
    float Pp = 1.f;

    const int bl0 = b*LL + g*CLEN;

    for (int t0=0; t0<CLEN; t0+=16) {
        __syncthreads();
        for (int q=threadIdx.x; q<16*XDW; q+=128) {
            int j = q >> 6, m = q & 63;
            sX[j][m] = xdbl[(bl0+t0+j)*XDW + m];
        }
        __syncthreads();
        for (int t=0;t<16;t++) {
            int idx = bl0 + t0 + t;
            float v = bd;
            #pragma unroll
            for (int r=0;r<DTR;r++) v = fmaf(sX[t][r], Wr[r], v);
            float ldt = fsoftplus(v);
            float s   = ldt * __half2float(u[(size_t)idx*DI + d]);
            if (fast) {
                float p = fexp(ldt*A[0]);
                Pp *= p;
                float pw = p;
                #pragma unroll
                for (int n=0;n<DS;n++) { h[n] = fmaf(pw, h[n], s*sX[t][DTR+n]); pw *= p; }
            } else {
                #pragma unroll
                for (int n=0;n<DS;n++) {
                    float a = fexp(ldt*A[n]);
                    ap[n] *= a;
                    h[n] = fmaf(a, h[n], s*sX[t][DTR+n]);
                }
            }
        }
    }
    if (fast) {
        float pw = Pp;
        #pragma unroll
        for (int n=0;n<DS;n++) { ap[n] = pw; pw *= Pp; }
    }
    #pragma unroll
    for (int n=0;n<DS;n++) {
        E[(g*DS+n)*NCHAIN + chain] = h[n];
        P[(g*DS+n)*NCHAIN + chain] = ap[n];
    }
}

__global__ void scan_phaseB(const float* __restrict__ E,
                            const float* __restrict__ P,
                            float* __restrict__ Hi)
{
    int c = blockIdx.x*256 + threadIdx.x;
    if (c >= NCHAIN) return;
    #pragma unroll
    for (int n=0;n<DS;n++) {
        float carry = 0.f;
        #pragma unroll
        for (int g=0;g<NCHUNK;g++) {
            int o = (g*DS+n)*NCHAIN + c;
            Hi[o] = carry;
            carry = fmaf(P[o], carry, E[o]);
        }
    }
}

__global__ __launch_bounds__(128)
void scan_phaseC(const __half* __restrict__ u,
                 const float* __restrict__ xdbl,
                 const __half* __restrict__ xz,
                 const float* __restrict__ Wdt,
                 const float* __restrict__ bdt,
                 const float* __restrict__ Alog,
                 const float* __restrict__ Dpar,
                 const float* __restrict__ Hi,
                 __half* __restrict__ yout)
{
    const int d = blockIdx.x*128 + threadIdx.x;
    const int g = blockIdx.y;
    const int b = blockIdx.z;
    const int chain = b*DI + d;

    __shared__ float sW[128*33];
    __shared__ float sX[16][XDW];

    {
        const float* wsrc = Wdt + (size_t)(blockIdx.x*128)*DTR;
        for (int idx = threadIdx.x; idx < 128*DTR; idx += 128) {
            int j = idx >> 5, r = idx & 31;
            sW[j*33 + r] = wsrc[idx];
        }
    }
    __syncthreads();
    float Wr[DTR];
    #pragma unroll
    for (int r=0;r<DTR;r++) Wr[r] = sW[threadIdx.x*33 + r];
    const float bd = bdt[d];

    float A[DS];
    #pragma unroll
    for (int n=0;n<DS;n++) A[n] = -fexp(Alog[d*DS+n]);
    bool fast = true;
    #pragma unroll
    for (int n=1;n<DS;n++)
        fast = fast && (fabsf(A[n] - A[0]*(float)(n+1)) <= 1e-4f*fabsf(A[n]) + 1e-6f);

    float h[DS];
    #pragma unroll
    for (int n=0;n<DS;n++) h[n] = Hi[(g*DS+n)*NCHAIN + chain];
    const float Dp = Dpar[d];

    const int bl0 = b*LL + g*CLEN;

    for (int t0=0; t0<CLEN; t0+=16) {
        __syncthreads();
        for (int q=threadIdx.x; q<16*XDW; q+=128) {
            int j = q >> 6, m = q & 63;
            sX[j][m] = xdbl[(bl0+t0+j)*XDW + m];
        }
        __syncthreads();
        for (int t=0;t<16;t++) {
            int idx = bl0 + t0 + t;
            float v = bd;
            #pragma unroll
            for (int r=0;r<DTR;r++) v = fmaf(sX[t][r], Wr[r], v);
            float ldt = fsoftplus(v);
            float lu  = __half2float(u[(size_t)idx*DI + d]);
            float s   = ldt * lu;
            float y   = 0.f;
            if (fast) {
                float p = fexp(ldt*A[0]);
                float pw = p;
                #pragma unroll
                for (int n=0;n<DS;n++) {
                    h[n] = fmaf(pw, h[n], s*sX[t][DTR+n]);
                    y    = fmaf(h[n], sX[t][DTR+DS+n], y);
                    pw *= p;
                }
            } else {
                #pragma unroll
                for (int n=0;n<DS;n++) {
                    float a = fexp(ldt*A[n]);
                    h[n] = fmaf(a, h[n], s*sX[t][DTR+n]);
                    y    = fmaf(h[n], sX[t][DTR+DS+n], y);
                }
            }
            float z = __half2float(xz[(size_t)idx*(2*DI) + DI + d]);
            yout[(size_t)idx*DI + d] = __float2half((y + lu*Dp) * z * fsigmoid(z));
        }
    }
}

// ---------------------------------------------------------------------------
// Head (fp16 x input)
// ---------------------------------------------------------------------------
__global__ void head_kernel(const __half* __restrict__ x,
                            const int* __restrict__ lens,
                            const float* __restrict__ W1,
                            const float* __restrict__ b1,
                            const float* __restrict__ W2,
                            const float* __restrict__ b2,
                            float* __restrict__ out)
{
    __shared__ float xs[DM];
    __shared__ float red[DHID];
    const int b = blockIdx.x;
    const int tid = threadIdx.x;
    const int l = lens[b] - 1;
    const __half* xr = x + ((size_t)(b*LL + l))*DM;
    for (int i=tid; i<DM; i+=DHID) xs[i] = __half2float(xr[i]);
    __syncthreads();
    float acc = b1[tid];
    const float* w = W1 + tid*DM;
    #pragma unroll 4
    for (int d0=0; d0<DM; d0+=4) {
        float4 wv = *(const float4*)(w + d0);
        acc = fmaf(wv.x, xs[d0+0], acc);
        acc = fmaf(wv.y, xs[d0+1], acc);
        acc = fmaf(wv.z, xs[d0+2], acc);
        acc = fmaf(wv.w, xs[d0+3], acc);
    }
    float hh = fmaxf(acc, 0.f);
    red[tid] = hh * W2[tid];
    __syncthreads();
    for (int s=DHID/2; s>0; s>>=1) {
        if (tid < s) red[tid] += red[tid+s];
        __syncthreads();
    }
    if (tid == 0) out[b] = red[0] + b2[0];
}

// ---------------------------------------------------------------------------
// Host launcher
// ---------------------------------------------------------------------------
extern "C" void kernel_launch(void* const* d_in, const int* in_sizes, int n_in,
                              void* d_out, int out_size)
{
    const int*   rna     = (const int*)  d_in[0];
    const int*   tissue  = (const int*)  d_in[1];
    const int*   lens    = (const int*)  d_in[2];
    const float* seq_emb = (const float*)d_in[3];
    const float* tis_emb = (const float*)d_in[4];
    const float* W_in    = (const float*)d_in[5];
    const float* conv_w  = (const float*)d_in[6];
    const float* conv_b  = (const float*)d_in[7];
    const float* W_xp    = (const float*)d_in[8];
    const float* W_dt    = (const float*)d_in[9];
    const float* b_dt    = (const float*)d_in[10];
    const float* A_log   = (const float*)d_in[11];
    const float* D_par   = (const float*)d_in[12];
    const float* W_out   = (const float*)d_in[13];
    const float* W1      = (const float*)d_in[14];
    const float* b1      = (const float*)d_in[15];
    const float* W2      = (const float*)d_in[16];
    const float* b2      = (const float*)d_in[17];

    __half *px0, *px1, *pxz, *pu, *py, *pWhin, *pWhxp, *pWhout;
    float  *pxd, *pE, *pP, *pHi;
    cudaGetSymbolAddress((void**)&px0,   g_x0);
    cudaGetSymbolAddress((void**)&px1,   g_x1);
    cudaGetSymbolAddress((void**)&pxz,   g_xz);
    cudaGetSymbolAddress((void**)&pu,    g_u);
    cudaGetSymbolAddress((void**)&pxd,   g_xdbl);
    cudaGetSymbolAddress((void**)&py,    g_y);
    cudaGetSymbolAddress((void**)&pE,    g_E);
    cudaGetSymbolAddress((void**)&pP,    g_P);
    cudaGetSymbolAddress((void**)&pHi,   g_Hi);
    cudaGetSymbolAddress((void**)&pWhin, g_Whin);
    cudaGetSymbolAddress((void**)&pWhxp, g_Whxp);
    cudaGetSymbolAddress((void**)&pWhout,g_Whout);

    cudaFuncSetAttribute((gemm_h<128,128,32,64,64,128,__half>),
                         cudaFuncAttributeMaxDynamicSharedMemorySize, GH_BIG_SMEM);
    cudaFuncSetAttribute((gemm_h<64,64,64,32,32,128,float>),
                         cudaFuncAttributeMaxDynamicSharedMemorySize, GH_XP_SMEM);

    // weight conversion (every launch; deterministic)
    {
        int n1 = NL*2*DI*DM, n2 = NL*XDW*DI, n3 = NL*DM*DI;
        cvt_kernel<<<(n1+255)/256, 256>>>(W_in,  pWhin,  n1);
        cvt_kernel<<<(n2+255)/256, 256>>>(W_xp,  pWhxp,  n2);
        cvt_kernel<<<(n3+255)/256, 256>>>(W_out, pWhout, n3);
    }

    embed_kernel<<<(BLTOT*DM+255)/256, 256>>>(rna, tissue, seq_emb, tis_emb, px0);

    __half* xin  = px0;
    __half* xout = px1;
    for (int i=0; i<NL; i++) {
        // in-proj: [16384,512](h) x [2048,512]^T(h) -> xz(h)
        gemm_h<128,128,32,64,64,128,__half>
            <<<dim3((2*DI)/128, BLTOT/128), 128, GH_BIG_SMEM>>>(
            xin, DM, pWhin + (size_t)i*2*DI*DM, DM, pxz, 2*DI, DM);
        // conv + silu -> u (h)
        conv_silu_kernel<<<(BLTOT*DI+255)/256, 256>>>(
            pxz, conv_w + i*DI*DCONV, conv_b + i*DI, pu);
        // x-proj: [16384,1024](h) x [64,1024]^T(h) -> xdbl (f32)
        gemm_h<64,64,64,32,32,128,float>
            <<<dim3(XDW/64, BLTOT/64), 128, GH_XP_SMEM>>>(
            pu, DI, pWhxp + (size_t)i*XDW*DI, DI, pxd, XDW, DI);
        // selective scan (dt fused)
        scan_phaseA<<<dim3(DI/128, NCHUNK, BB), 128>>>(
            pu, pxd, W_dt + (size_t)i*DI*DTR, b_dt + i*DI,
            A_log + (size_t)i*DI*DS, pE, pP);
        scan_phaseB<<<(NCHAIN+255)/256, 256>>>(pE, pP, pHi);
        scan_phaseC<<<dim3(DI/128, NCHUNK, BB), 128>>>(
            pu, pxd, pxz, W_dt + (size_t)i*DI*DTR, b_dt + i*DI,
            A_log + (size_t)i*DI*DS, D_par + i*DI, pHi, py);
        // out-proj: [16384,1024](h) x [512,1024]^T(h) -> x_next (h)
        gemm_h<128,128,32,64,64,128,__half>
            <<<dim3(DM/128, BLTOT/128), 128, GH_BIG_SMEM>>>(
            py, DI, pWhout + (size_t)i*DM*DI, DI, xout, DM, DI);

        __half* tmp = xin; xin = xout; xout = tmp;
    }

    head_kernel<<<BB, DHID>>>(xin, lens, W1, b1, W2, b2, (float*)d_out);
}